// round 12
// baseline (speedup 1.0000x reference)
#include <cuda_runtime.h>
#include <cuda_bf16.h>
#include <cstdint>

// ---------------- problem constants ----------------
#define NB   2
#define NN   192
#define IND  20
#define DIMD 128
#define HH   8
#define DHH  16
#define C2C  256
#define NSP  (NN*NN)            // 36864
#define C2TOT (NB*C2C*NSP)      // 18874368

// ---------------- scratch (device globals; no allocation allowed) ----------------
__device__ float g_xA[NB*NN*DIMD];
__device__ float g_xB[NB*NN*DIMD];
__device__ float g_cA[NB*DIMD*NN];
__device__ float g_cB[NB*DIMD*NN];
__device__ float g_q[NB*HH*NN*DHH];
__device__ float g_k[NB*HH*NN*DHH];
__device__ float g_v[NB*HH*NN*DHH];
__device__ float g_upd[NB*NN*DIMD];
__device__ float g_G[NB*HH*NSP];
__device__ float g_scale[C2C];
__device__ float g_shift[C2C];
__device__ float g_c2A[C2TOT];     // layer-0 initial pair state only
__device__ float g_c2X[C2TOT];     // raw conv2d output (pre-BN)
// int8 two-level quantized conv weights: [ocblk4][icc8][tap9][icquad8][oc64] u32 (4 ic per u32)
__device__ unsigned g_Wh[C2C*C2C*9/4];
__device__ unsigned g_Wl[C2C*C2C*9/4];
// int8 two-level quantized conv input: [b2][icquad64][row192][j192] u32
#define BQTOT (NB*64*NN*NN)     // 4718592
__device__ unsigned g_Bh[BQTOT];
__device__ unsigned g_Bl[BQTOT];
// scales
__device__ float g_Sw[C2C];        // weight scale per oc
__device__ float g_invSw[C2C];
__device__ float g_Sa;             // input scale (global)
__device__ float g_invSa;
__device__ unsigned g_statemax_u;  // float bits, values >= 0
__device__ unsigned g_cmax_u;

__device__ __forceinline__ float warp_max(float v) {
    #pragma unroll
    for (int o = 16; o; o >>= 1) v = fmaxf(v, __shfl_xor_sync(0xffffffffu, v, o));
    return v;
}
__device__ __forceinline__ int clamp127(float t) {
    int q = (int)rintf(t);
    return q > 127 ? 127 : (q < -127 ? -127 : q);
}

// =================================================================
// tiny reset / scale-combine kernels
// =================================================================
__global__ void k_rst() { g_statemax_u = 0u; g_cmax_u = 0u; }

__global__ void k_sa()
{
    float amax = __uint_as_float(g_statemax_u) + __uint_as_float(g_cmax_u);
    if (!(amax > 1e-30f)) amax = 1e-30f;
    g_Sa = amax * (1.f/127.f);
    g_invSa = 127.f / amax;
    g_statemax_u = 0u;
    g_cmax_u = 0u;
}

// =================================================================
// Stem: x = conv1d(seq^T, conv1_w)^T ; c = conv1d(seq^T, conv2_w)
// also accumulates max|c| into g_statemax_u (layer-0 state bound)
// =================================================================
__global__ void k_stem(const float* __restrict__ seq,
                       const float* __restrict__ w1,
                       const float* __restrict__ w2)
{
    int n = blockIdx.x, b = blockIdx.y, d = threadIdx.x;
    __shared__ float s3[3][IND];
    if (d < 3*IND) {
        int r = d / IND, ic = d % IND;
        int nn = n - 1 + r;
        s3[r][ic] = (nn >= 0 && nn < NN) ? seq[(b*NN + nn)*IND + ic] : 0.f;
    }
    __syncthreads();
    float ax = 0.f, ac = 0.f;
    #pragma unroll
    for (int ic = 0; ic < IND; ++ic) {
        #pragma unroll
        for (int r = 0; r < 3; ++r) {
            float v = s3[r][ic];
            ax += v * w1[(d*IND + ic)*3 + r];
            ac += v * w2[(d*IND + ic)*3 + r];
        }
    }
    g_xA[(b*NN + n)*DIMD + d] = ax;
    g_cA[(b*DIMD + d)*NN + n] = ac;
    float m = warp_max(fabsf(ac));
    if ((d & 31) == 0) atomicMax(&g_statemax_u, __float_as_uint(m));
}

// =================================================================
// init pair state:  c2A = seq2pair(cA)
// =================================================================
__global__ void k_pair0()
{
    int idx = blockIdx.x * blockDim.x + threadIdx.x;
    int j  = idx % NN;
    int r1 = idx / NN;
    int i  = r1 % NN;
    int r2 = r1 / NN;
    int ch = r2 % C2C;
    int b  = r2 / C2C;
    float pv = (ch < DIMD) ? g_cA[(b*DIMD + ch)*NN + i]
                           : g_cA[(b*DIMD + (ch - DIMD))*NN + j];
    g_c2A[idx] = pv;
}

// =================================================================
// c = relu(bn1(conv1d(c, c1d_w[l])))  — chunked smem staging.
// also accumulates max(c_out) into g_cmax_u
// =================================================================
__global__ void __launch_bounds__(384)
k_conv1bn(int rd, const float* __restrict__ w,
          const float* __restrict__ gg, const float* __restrict__ bb)
{
    int d = blockIdx.x;
    int t = threadIdx.x;
    int b = t / NN, n = t % NN;
    const float* c  = rd ? g_cB : g_cA;
    float*       co = rd ? g_cA : g_cB;

    __shared__ float sc[16][2][194];
    __shared__ float wsh[DIMD*3];
    __shared__ float red[2][12];

    wsh[t] = w[d*DIMD*3 + t];
    if (t < 32) { sc[t >> 1][t & 1][0] = 0.f; sc[t >> 1][t & 1][193] = 0.f; }
    __syncthreads();

    float acc = 0.f;
    for (int ec = 0; ec < DIMD; ec += 16) {
        #pragma unroll
        for (int q = 0; q < 16; ++q) {
            int s = q*384 + t;
            int e1 = s / 384;
            int rem = s - e1*384;
            int bb2 = rem / NN, n2 = rem - bb2*NN;
            sc[e1][bb2][n2 + 1] = c[((bb2*DIMD) + ec + e1)*NN + n2];
        }
        __syncthreads();
        #pragma unroll
        for (int e1 = 0; e1 < 16; ++e1) {
            int e = ec + e1;
            acc += sc[e1][b][n]     * wsh[e*3 + 0]
                 + sc[e1][b][n + 1] * wsh[e*3 + 1]
                 + sc[e1][b][n + 2] * wsh[e*3 + 2];
        }
        __syncthreads();
    }

    float s = acc, ss = acc * acc;
    #pragma unroll
    for (int o = 16; o; o >>= 1) {
        s  += __shfl_down_sync(0xffffffffu, s,  o);
        ss += __shfl_down_sync(0xffffffffu, ss, o);
    }
    if (!(t & 31)) { red[0][t >> 5] = s; red[1][t >> 5] = ss; }
    __syncthreads();
    float ts = 0.f, tss = 0.f;
    #pragma unroll
    for (int ww = 0; ww < 12; ++ww) { ts += red[0][ww]; tss += red[1][ww]; }
    float mean = ts * (1.f/384.f);
    float var  = tss * (1.f/384.f) - mean*mean;
    float inv  = rsqrtf(var + 1e-5f);

    float outv = fmaxf((acc - mean) * inv * gg[d] + bb[d], 0.f);
    co[(b*DIMD + d)*NN + n] = outv;
    float m = warp_max(outv);
    if ((t & 31) == 0) atomicMax(&g_cmax_u, __float_as_uint(m));
}

// =================================================================
// x = LN(x + c^T)
// =================================================================
__global__ void k_ln(int xs, int cs,
                     const float* __restrict__ gg, const float* __restrict__ bb)
{
    int n = blockIdx.x, b = blockIdx.y, d = threadIdx.x;
    float*       x = xs ? g_xB : g_xA;
    const float* c = cs ? g_cB : g_cA;

    float v = x[(b*NN + n)*DIMD + d] + c[(b*DIMD + d)*NN + n];

    __shared__ float red[2][4];
    float s = v, ss = v*v;
    #pragma unroll
    for (int o = 16; o; o >>= 1) {
        s  += __shfl_down_sync(0xffffffffu, s,  o);
        ss += __shfl_down_sync(0xffffffffu, ss, o);
    }
    if (!(d & 31)) { red[0][d >> 5] = s; red[1][d >> 5] = ss; }
    __syncthreads();
    float m   = (red[0][0]+red[0][1]+red[0][2]+red[0][3]) * (1.f/128.f);
    float var = (red[1][0]+red[1][1]+red[1][2]+red[1][3]) * (1.f/128.f) - m*m;
    float inv = rsqrtf(var + 1e-5f);
    x[(b*NN + n)*DIMD + d] = (v - m) * inv * gg[d] + bb[d];
}

// =================================================================
// per-oc weight absmax -> g_Sw, g_invSw.  256 blocks x 256 threads.
// =================================================================
__global__ void k_wmax(const float* __restrict__ w)
{
    int oc = blockIdx.x, t = threadIdx.x;
    const float* p = w + oc*2304;
    float m = 0.f;
    #pragma unroll
    for (int e = 0; e < 9; ++e) m = fmaxf(m, fabsf(p[t*9 + e]));
    m = warp_max(m);
    __shared__ float red[8];
    if (!(t & 31)) red[t >> 5] = m;
    __syncthreads();
    if (t == 0) {
        float mm = 0.f;
        #pragma unroll
        for (int ww = 0; ww < 8; ++ww) mm = fmaxf(mm, red[ww]);
        if (mm > 0.f) { g_Sw[oc] = mm * (1.f/127.f); g_invSw[oc] = 127.f / mm; }
        else          { g_Sw[oc] = 0.f;              g_invSw[oc] = 0.f; }
    }
}

// =================================================================
// quantize conv2d weights -> int8 hi/lo, packed 4 ic per u32.
// layout [ocblk4][icc8][tap9][icquad8][oc64].  grid 576 x 256 (147456 u32).
// =================================================================
__global__ void k_splitw(const float* __restrict__ w)   // w: [256][256][9]
{
    int o = blockIdx.x * 256 + threadIdx.x;             // 0..147455 exact
    int oc    = o & 63;
    int quad  = (o >> 6) & 7;
    int tap   = (o >> 9) % 9;
    int icc   = (o / 4608) & 7;
    int ocblk = o / 36864;
    int ocg = ocblk*64 + oc;
    int ic0 = icc*32 + quad*4;
    float inv = g_invSw[ocg];
    unsigned vh = 0u, vl = 0u;
    #pragma unroll
    for (int e = 0; e < 4; ++e) {
        float t = w[(ocg*C2C + ic0 + e)*9 + tap] * inv;
        int qh = clamp127(t);
        int ql = clamp127((t - (float)qh) * 256.f);
        vh |= ((unsigned)(unsigned char)(signed char)qh) << (8*e);
        vl |= ((unsigned)(unsigned char)(signed char)ql) << (8*e);
    }
    g_Wh[o] = vh;
    g_Wl[o] = vl;
}

// =================================================================
// prep conv2d input: v = state + seq2pair(c_cur); state = c2A (mode 0)
// or relu(bn_prev(c2X)) (mode 1).  Quantize int8 hi/lo, pack 4 ic per u32.
// layout [b][icquad64][row][j].  grid 18432 x 256.
// =================================================================
__global__ void k_prep(int csel, int mode)
{
    int idx = blockIdx.x * 256 + threadIdx.x;      // 0..BQTOT-1
    int j    = idx % NN;
    int r1   = idx / NN;
    int row  = r1 % NN;
    int r2   = r1 / NN;
    int quad = r2 % 64;
    int b    = r2 / 64;
    const float* cc = csel ? g_cB : g_cA;
    float invSa = g_invSa;

    unsigned vh = 0u, vl = 0u;
    #pragma unroll
    for (int e = 0; e < 4; ++e) {
        int ic = quad*4 + e;
        size_t sidx = ((size_t)(b*C2C + ic)*NN + row)*NN + j;
        float st;
        if (mode) st = fmaxf(fmaf(g_c2X[sidx], g_scale[ic], g_shift[ic]), 0.f);
        else      st = g_c2A[sidx];
        float v = st + ((ic < DIMD) ? cc[(b*DIMD + ic)*NN + row]
                                    : cc[(b*DIMD + ic - DIMD)*NN + j]);
        float t = v * invSa;
        int qh = clamp127(t);
        int ql = clamp127((t - (float)qh) * 256.f);
        vh |= ((unsigned)(unsigned char)(signed char)qh) << (8*e);
        vl |= ((unsigned)(unsigned char)(signed char)ql) << (8*e);
    }
    g_Bh[idx] = vh;
    g_Bl[idx] = vl;
}

// =================================================================
// conv2d 3x3 C2->C2 on int8 tensor cores (two-level, mma.m16n8k32.s8).
// Raw fp32 out -> g_c2X.
// CTA: 64 oc x output row i x batch.  8 warps: 32 oc x 48 j each.
// K loop: 8 chunks of 32 ic (8 quads); 9 taps per chunk.
// Smem (u32): Ah/Al [tap9][quad8][stride 72]  (5184 each)
//             Bh/Bl [r3*quad8][stride 200]    (4800 each), data at col 4..195
// =================================================================
#define MMA_S8(c0,c1,c2,c3, A0,A1,A2,A3, B0,B1)                           \
  asm volatile("mma.sync.aligned.m16n8k32.row.col.s32.s8.s8.s32 "         \
    "{%0,%1,%2,%3},{%4,%5,%6,%7},{%8,%9},{%0,%1,%2,%3};"                  \
    : "+r"(c0),"+r"(c1),"+r"(c2),"+r"(c3)                                 \
    : "r"(A0),"r"(A1),"r"(A2),"r"(A3),"r"(B0),"r"(B1))

#define ASZ 5184
#define BSZ 4800
#define CONV_SMEM ((2*ASZ + 2*BSZ)*4)   // 79872 B

__global__ void __launch_bounds__(256, 1)
k_conv2d_mma()
{
    extern __shared__ unsigned smu[];
    unsigned* Ah = smu;
    unsigned* Al = smu + ASZ;
    unsigned* Bh = smu + 2*ASZ;
    unsigned* Bl = smu + 2*ASZ + BSZ;

    int ocblk = blockIdx.x;       // 0..3
    int i     = blockIdx.y;       // 0..191
    int b     = blockIdx.z;       // 0..1
    int t = threadIdx.x;
    int w = t >> 5, lane = t & 31;
    int g = lane >> 2, tig = lane & 3;
    int wm = w & 1, wn = w >> 1;

    // zero B halo columns (written once, outside data range)
    if (t < 192) {
        int rr = t / 8, cq = t & 7;
        int col = (cq < 4) ? cq : (192 + cq);
        Bh[rr*200 + col] = 0u;
        Bl[rr*200 + col] = 0u;
    }

    int accH[2][6][4], accC[2][6][4];
    #pragma unroll
    for (int m = 0; m < 2; ++m)
        #pragma unroll
        for (int u = 0; u < 6; ++u)
            #pragma unroll
            for (int q = 0; q < 4; ++q) { accH[m][u][q] = 0; accC[m][u][q] = 0; }

    const unsigned* whsrc = g_Wh + ocblk*36864;
    const unsigned* wlsrc = g_Wl + ocblk*36864;

    for (int icc = 0; icc < 8; ++icc) {
        // ---- stage weights: 2 x 1152 uint4 ----
        #pragma unroll
        for (int q = 0; q < 9; ++q) {
            int sidx = q*256 + t;
            int hl = sidx >= 1152;
            int s2 = hl ? sidx - 1152 : sidx;
            int s4 = s2 * 4;
            int tap = s4 >> 9, p = (s4 >> 6) & 7, oc = s4 & 63;
            int dst = ((tap*8 + p)*72 + oc) >> 2;
            const uint4 v = ((const uint4*)(hl ? wlsrc : whsrc))[icc*1152 + s2];
            ((uint4*)(hl ? Al : Ah))[dst] = v;
        }
        // ---- stage input: 2 x 24 segs x 48 uint4 ----
        #pragma unroll
        for (int q = 0; q < 9; ++q) {
            int sidx = q*256 + t;
            int hl = sidx >= 1152;
            int s2 = hl ? sidx - 1152 : sidx;
            int seg = s2 / 48, v4 = s2 - seg*48;   // seg = r*8+quad
            int r = seg >> 3, quad = seg & 7;
            int row = i - 1 + r;
            uint4 val = make_uint4(0u,0u,0u,0u);
            if (row >= 0 && row < NN)
                val = ((const uint4*)(hl ? g_Bl : g_Bh))
                        [(size_t)((b*64 + icc*8 + quad)*NN + row)*48 + v4];
            ((uint4*)(hl ? Bl : Bh))[(seg*200 + 4 + v4*4) >> 2] = val;
        }
        __syncthreads();

        #pragma unroll
        for (int r = 0; r < 3; ++r) {
            #pragma unroll
            for (int dj = 0; dj < 3; ++dj) {
                int tap = r*3 + dj;
                unsigned ah[2][4], al[2][4];
                #pragma unroll
                for (int m = 0; m < 2; ++m) {
                    int mb = wm*32 + m*16 + g;
                    ah[m][0] = Ah[(tap*8 + tig    )*72 + mb    ];
                    ah[m][1] = Ah[(tap*8 + tig    )*72 + mb + 8];
                    ah[m][2] = Ah[(tap*8 + tig + 4)*72 + mb    ];
                    ah[m][3] = Ah[(tap*8 + tig + 4)*72 + mb + 8];
                    al[m][0] = Al[(tap*8 + tig    )*72 + mb    ];
                    al[m][1] = Al[(tap*8 + tig    )*72 + mb + 8];
                    al[m][2] = Al[(tap*8 + tig + 4)*72 + mb    ];
                    al[m][3] = Al[(tap*8 + tig + 4)*72 + mb + 8];
                }
                #pragma unroll
                for (int u = 0; u < 6; ++u) {
                    int col = wn*48 + u*8 + g + dj + 3;
                    unsigned bh0 = Bh[(r*8 + tig    )*200 + col];
                    unsigned bh1 = Bh[(r*8 + tig + 4)*200 + col];
                    unsigned bl0 = Bl[(r*8 + tig    )*200 + col];
                    unsigned bl1 = Bl[(r*8 + tig + 4)*200 + col];
                    #pragma unroll
                    for (int m = 0; m < 2; ++m) {
                        int* cH = accH[m][u];
                        int* cC = accC[m][u];
                        MMA_S8(cH[0],cH[1],cH[2],cH[3],
                               ah[m][0],ah[m][1],ah[m][2],ah[m][3], bh0,bh1);
                        MMA_S8(cC[0],cC[1],cC[2],cC[3],
                               ah[m][0],ah[m][1],ah[m][2],ah[m][3], bl0,bl1);
                        MMA_S8(cC[0],cC[1],cC[2],cC[3],
                               al[m][0],al[m][1],al[m][2],al[m][3], bh0,bh1);
                    }
                }
            }
        }
        __syncthreads();
    }

    // ---- epilogue: dequantize to fp32, write raw conv output ----
    float sa = g_Sa;
    #pragma unroll
    for (int m = 0; m < 2; ++m) {
        int oc0 = ocblk*64 + wm*32 + m*16 + g;
        float f0 = sa * g_Sw[oc0];
        float f8 = sa * g_Sw[oc0 + 8];
        #pragma unroll
        for (int u = 0; u < 6; ++u) {
            int j = wn*48 + u*8 + 2*tig;
            float v0 = ((float)accH[m][u][0] + (float)accC[m][u][0]*(1.f/256.f)) * f0;
            float v1 = ((float)accH[m][u][1] + (float)accC[m][u][1]*(1.f/256.f)) * f0;
            float v2 = ((float)accH[m][u][2] + (float)accC[m][u][2]*(1.f/256.f)) * f8;
            float v3 = ((float)accH[m][u][3] + (float)accC[m][u][3]*(1.f/256.f)) * f8;
            *(float2*)&g_c2X[((size_t)(b*C2C + oc0    )*NN + i)*NN + j] = make_float2(v0, v1);
            *(float2*)&g_c2X[((size_t)(b*C2C + oc0 + 8)*NN + i)*NN + j] = make_float2(v2, v3);
        }
    }
}

// =================================================================
// BN2 stats on raw conv output g_c2X; also next-layer state max bound.
// =================================================================
__global__ void k_bnstats(const float* __restrict__ gg, const float* __restrict__ bb)
{
    int oc = blockIdx.x, t = threadIdx.x;
    float s = 0.f, ss = 0.f, vmx = -3e38f, vmn = 3e38f;
    for (int b = 0; b < NB; ++b) {
        const float* p = g_c2X + (size_t)(b*C2C + oc)*NSP;
        for (int k = t; k < NSP; k += 256) {
            float v = p[k];
            s += v; ss += v*v;
            vmx = fmaxf(vmx, v); vmn = fminf(vmn, v);
        }
    }
    __shared__ float red[4][8];
    #pragma unroll
    for (int o = 16; o; o >>= 1) {
        s   += __shfl_down_sync(0xffffffffu, s,  o);
        ss  += __shfl_down_sync(0xffffffffu, ss, o);
        vmx  = fmaxf(vmx, __shfl_down_sync(0xffffffffu, vmx, o));
        vmn  = fminf(vmn, __shfl_down_sync(0xffffffffu, vmn, o));
    }
    if (!(t & 31)) { red[0][t>>5]=s; red[1][t>>5]=ss; red[2][t>>5]=vmx; red[3][t>>5]=vmn; }
    __syncthreads();
    if (t == 0) {
        float ts = 0.f, tss = 0.f, tmx = -3e38f, tmn = 3e38f;
        #pragma unroll
        for (int ww = 0; ww < 8; ++ww) {
            ts += red[0][ww]; tss += red[1][ww];
            tmx = fmaxf(tmx, red[2][ww]); tmn = fminf(tmn, red[3][ww]);
        }
        float mean = ts * (1.f / (NB*NSP));
        float var  = tss * (1.f / (NB*NSP)) - mean*mean;
        float inv  = rsqrtf(var + 1e-5f);
        float sc = inv * gg[oc];
        float sh = bb[oc] - mean * sc;
        g_scale[oc] = sc;
        g_shift[oc] = sh;
        float bound = fmaxf(fmaxf(tmx*sc + sh, tmn*sc + sh), 0.f);
        atomicMax(&g_statemax_u, __float_as_uint(bound));
    }
}

// =================================================================
// gate logits with BN+relu applied inline from raw c2X
// =================================================================
__global__ void k_gate(const float* __restrict__ wd)
{
    int i = blockIdx.x, b = blockIdx.y, j = threadIdx.x;
    __shared__ float wsh[C2C*HH];
    __shared__ float scs[C2C], shs[C2C];
    for (int s = j; s < C2C*HH; s += NN) {
        int c = s >> 3, h = s & 7;
        wsh[s] = wd[h*C2C + c];
    }
    for (int s = j; s < C2C; s += NN) { scs[s] = g_scale[s]; shs[s] = g_shift[s]; }
    __syncthreads();
    float acc[HH] = {};
    const float* base = g_c2X + (size_t)(b*C2C)*NSP + i*NN + j;
    #pragma unroll 4
    for (int c = 0; c < C2C; ++c) {
        float v = fmaxf(fmaf(base[(size_t)c*NSP], scs[c], shs[c]), 0.f);
        #pragma unroll
        for (int h = 0; h < HH; ++h) acc[h] += v * wsh[c*8 + h];
    }
    #pragma unroll
    for (int h = 0; h < HH; ++h)
        g_G[((b*HH + h)*NN + i)*NN + j] = acc[h];
}

// =================================================================
// Generic 384x128x128 GEMM with relu epilogue.
// =================================================================
__global__ void k_gemm64(int asel, int addupd,
                         const float* __restrict__ W,
                         const float* __restrict__ bias,
                         int outsel, float* dptr)
{
    __shared__ float As[32*68];
    __shared__ float Ws[32*68];
    int t = threadIdx.x;
    int tx = t & 15, ty = t >> 4;
    int rowbase = blockIdx.y * 64, colbase = blockIdx.x * 64;

    const float* A = asel ? g_xB : g_xA;
    float* outp; int headed = 0;
    if      (outsel == 0) { outp = g_q; headed = 1; }
    else if (outsel == 1) { outp = g_k; headed = 1; }
    else if (outsel == 2) { outp = g_v; headed = 1; }
    else if (outsel == 3) { outp = g_xA; }
    else if (outsel == 4) { outp = g_xB; }
    else                  { outp = dptr; }

    float acc[4][4] = {};
    for (int kk = 0; kk < 128; kk += 32) {
        #pragma unroll
        for (int r = 0; r < 8; ++r) {
            int s = r*256 + t;
            int row = s >> 5, e = s & 31;
            float v = A[(rowbase + row)*DIMD + kk + e];
            if (addupd) v += g_upd[(rowbase + row)*DIMD + kk + e];
            As[e*68 + row] = v;
            Ws[e*68 + row] = W[(colbase + row)*DIMD + kk + e];
        }
        __syncthreads();
        #pragma unroll
        for (int e = 0; e < 32; ++e) {
            float a0 = As[e*68 + ty*4 + 0], a1 = As[e*68 + ty*4 + 1];
            float a2 = As[e*68 + ty*4 + 2], a3 = As[e*68 + ty*4 + 3];
            float w0 = Ws[e*68 + tx*4 + 0], w1 = Ws[e*68 + tx*4 + 1];
            float w2 = Ws[e*68 + tx*4 + 2], w3 = Ws[e*68 + tx*4 + 3];
            acc[0][0] += a0*w0; acc[0][1] += a0*w1; acc[0][2] += a0*w2; acc[0][3] += a0*w3;
            acc[1][0] += a1*w0; acc[1][1] += a1*w1; acc[1][2] += a1*w2; acc[1][3] += a1*w3;
            acc[2][0] += a2*w0; acc[2][1] += a2*w1; acc[2][2] += a2*w2; acc[2][3] += a2*w3;
            acc[3][0] += a3*w0; acc[3][1] += a3*w1; acc[3][2] += a3*w2; acc[3][3] += a3*w3;
        }
        __syncthreads();
    }

    #pragma unroll
    for (int v = 0; v < 4; ++v) {
        int row = rowbase + ty*4 + v;
        #pragma unroll
        for (int u = 0; u < 4; ++u) {
            int col = colbase + tx*4 + u;
            float r = fmaxf(acc[v][u] + bias[col], 0.f);
            if (headed) {
                int b = row / NN, n = row % NN, h = col >> 4, dh = col & 15;
                outp[((b*HH + h)*NN + n)*DHH + dh] = r;
            } else {
                outp[row*DIMD + col] = r;
            }
        }
    }
}

// =================================================================
// Attention + gate
// =================================================================
__global__ void k_attn(const float* __restrict__ mask,
                       const float* __restrict__ wdb)
{
    int i = blockIdx.x, h = blockIdx.y, b = blockIdx.z;
    int t = threadIdx.x;
    int bh = b*HH + h;

    __shared__ float qi[DHH];
    __shared__ float att[NN];
    __shared__ float redm[8];
    __shared__ float reds[8];
    __shared__ float part[16][17];

    if (t < DHH) qi[t] = g_q[(bh*NN + i)*DHH + t];
    __syncthreads();

    float aval = 0.f;
    if (t < NN) {
        const float* kp = g_k + (bh*NN + t)*DHH;
        float s = 0.f;
        #pragma unroll
        for (int d = 0; d < DHH; ++d) s += qi[d] * kp[d];
        aval = s * 0.25f;
    }
    float mval = (t < NN) ? aval : -3e38f;
    #pragma unroll
    for (int o = 16; o; o >>= 1) mval = fmaxf(mval, __shfl_xor_sync(0xffffffffu, mval, o));
    if (!(t & 31)) redm[t >> 5] = mval;
    __syncthreads();
    float mx = redm[0];
    #pragma unroll
    for (int ww = 1; ww < 8; ++ww) mx = fmaxf(mx, redm[ww]);

    float e = (t < NN) ? expf(aval - mx) * mask[b*NN + t] : 0.f;
    float sv = e;
    #pragma unroll
    for (int o = 16; o; o >>= 1) sv += __shfl_xor_sync(0xffffffffu, sv, o);
    if (!(t & 31)) reds[t >> 5] = sv;
    __syncthreads();
    float den = 1e-6f;
    #pragma unroll
    for (int ww = 0; ww < 8; ++ww) den += reds[ww];

    if (t < NN) {
        float gl = g_G[(bh*NN + i)*NN + t] + g_G[(bh*NN + t)*NN + i] + wdb[h];
        float gate = 1.f / (1.f + expf(-gl));
        att[t] = (e / den) * gate;
    }
    __syncthreads();

    int d = t & 15, grp = t >> 4;
    float p = 0.f;
    #pragma unroll
    for (int jj = 0; jj < 12; ++jj) {
        int j = grp*12 + jj;
        p += att[j] * g_v[(bh*NN + j)*DHH + d];
    }
    part[grp][d] = p;
    __syncthreads();
    if (t < DHH) {
        float s = 0.f;
        #pragma unroll
        for (int gg = 0; gg < 16; ++gg) s += part[gg][t];
        g_upd[(b*NN + i)*DIMD + h*DHH + t] = s;
    }
}

// =================================================================
// host
// =================================================================
extern "C" void kernel_launch(void* const* d_in, const int* in_sizes, int n_in,
                              void* d_out, int out_size)
{
    const float* seq     = (const float*)d_in[0];
    const float* mask    = (const float*)d_in[1];
    const float* conv1_w = (const float*)d_in[2];
    const float* conv2_w = (const float*)d_in[3];
    const float* ln_g    = (const float*)d_in[4];
    const float* ln_b    = (const float*)d_in[5];
    const float* c1d_w   = (const float*)d_in[6];
    const float* bn1_g   = (const float*)d_in[7];
    const float* bn1_b   = (const float*)d_in[8];
    const float* c2d_w   = (const float*)d_in[9];
    const float* bn2_g   = (const float*)d_in[10];
    const float* bn2_b   = (const float*)d_in[11];
    const float* wq_w    = (const float*)d_in[12];
    const float* wq_b    = (const float*)d_in[13];
    const float* wk_w    = (const float*)d_in[14];
    const float* wk_b    = (const float*)d_in[15];
    const float* wv_w    = (const float*)d_in[16];
    const float* wv_b    = (const float*)d_in[17];
    const float* wd_w    = (const float*)d_in[18];
    const float* wd_b    = (const float*)d_in[19];
    const float* wl_w    = (const float*)d_in[20];
    const float* wl_b    = (const float*)d_in[21];
    const float* fc_w    = (const float*)d_in[22];
    const float* fc_b    = (const float*)d_in[23];
    float* out = (float*)d_out;

    static int smem_set = 0;
    if (!smem_set) {
        cudaFuncSetAttribute(k_conv2d_mma, cudaFuncAttributeMaxDynamicSharedMemorySize, CONV_SMEM);
        smem_set = 1;
    }

    k_rst<<<1, 1>>>();
    k_stem<<<dim3(NN, NB), 128>>>(seq, conv1_w, conv2_w);
    k_pair0<<<C2TOT/256, 256>>>();

    int xs = 0;
    for (int l = 0; l < 3; ++l) {
        int rd   = l & 1;        // which buffer holds incoming c
        int cnew = rd ^ 1;       // buffer that will hold new c

        k_conv1bn<<<DIMD, 384>>>(rd, c1d_w + l*DIMD*DIMD*3, bn1_g + l*DIMD, bn1_b + l*DIMD);
        k_ln<<<dim3(NN, NB), DIMD>>>(xs, cnew, ln_g + l*DIMD, ln_b + l*DIMD);
        k_wmax<<<C2C, 256>>>(c2d_w + l*C2C*C2C*9);
        k_splitw<<<576, 256>>>(c2d_w + l*C2C*C2C*9);
        k_sa<<<1, 1>>>();
        k_prep<<<BQTOT/256, 256>>>(cnew, l > 0 ? 1 : 0);
        k_conv2d_mma<<<dim3(4, NN, NB), 256, CONV_SMEM>>>();
        k_bnstats<<<C2C, 256>>>(bn2_g + l*C2C, bn2_b + l*C2C);
        k_gate<<<dim3(NN, NB), NN>>>(wd_w + l*HH*C2C);
        k_gemm64<<<dim3(2, 6), 256>>>(xs, 0, wq_w + l*DIMD*DIMD, wq_b + l*DIMD, 0, nullptr);
        k_gemm64<<<dim3(2, 6), 256>>>(xs, 0, wk_w + l*DIMD*DIMD, wk_b + l*DIMD, 1, nullptr);
        k_gemm64<<<dim3(2, 6), 256>>>(xs, 0, wv_w + l*DIMD*DIMD, wv_b + l*DIMD, 2, nullptr);
        k_attn<<<dim3(NN, HH, NB), 256>>>(mask, wd_b + l*HH);
        k_gemm64<<<dim3(2, 6), 256>>>(xs, 1, wl_w + l*DIMD*DIMD, wl_b + l*DIMD, xs ? 3 : 4, nullptr);
        xs ^= 1;
    }
    k_gemm64<<<dim3(2, 6), 256>>>(xs, 0, fc_w, fc_b, 5, out);
}

// round 13
// speedup vs baseline: 2.5878x; 2.5878x over previous
#include <cuda_runtime.h>
#include <cuda_bf16.h>
#include <cstdint>

// ---------------- problem constants ----------------
#define NB   2
#define NN   192
#define IND  20
#define DIMD 128
#define HH   8
#define DHH  16
#define C2C  256
#define NSP  (NN*NN)            // 36864
#define C2TOT (NB*C2C*NSP)      // 18874368

// ---------------- scratch (device globals; no allocation allowed) ----------------
__device__ float g_xA[NB*NN*DIMD];
__device__ float g_xB[NB*NN*DIMD];
__device__ float g_cA[NB*DIMD*NN];
__device__ float g_cB[NB*DIMD*NN];
__device__ float g_q[NB*HH*NN*DHH];
__device__ float g_k[NB*HH*NN*DHH];
__device__ float g_v[NB*HH*NN*DHH];
__device__ float g_upd[NB*NN*DIMD];
__device__ float g_G[NB*HH*NSP];
__device__ float g_scale[C2C];
__device__ float g_shift[C2C];
__device__ float g_bnsum[C2C];
__device__ float g_bnsq[C2C];
__device__ float g_c2A[C2TOT];     // layer-0 initial pair state only
__device__ float g_c2X[C2TOT];     // raw conv2d output (pre-BN)
// split conv2d weights, bf16 hi/lo packed (ic even | ic odd<<16)
// layout: [ocblk4][icc16][tap9][icpair8][oc64]
__device__ unsigned g_Wh[C2C*C2C*9/2];
__device__ unsigned g_Wl[C2C*C2C*9/2];
// pre-split conv2d INPUT, bf16 hi/lo packed by ic-pair: [b2][icpair128][row192][j192]
#define BPTOT (NB*128*NN*NN)    // 9437184
__device__ unsigned g_Bh[BPTOT];
__device__ unsigned g_Bl[BPTOT];

// =================================================================
// Stem: x = conv1d(seq^T, conv1_w)^T ; c = conv1d(seq^T, conv2_w)
// =================================================================
__global__ void k_stem(const float* __restrict__ seq,
                       const float* __restrict__ w1,
                       const float* __restrict__ w2)
{
    int n = blockIdx.x, b = blockIdx.y, d = threadIdx.x;
    __shared__ float s3[3][IND];
    if (d < 3*IND) {
        int r = d / IND, ic = d % IND;
        int nn = n - 1 + r;
        s3[r][ic] = (nn >= 0 && nn < NN) ? seq[(b*NN + nn)*IND + ic] : 0.f;
    }
    __syncthreads();
    float ax = 0.f, ac = 0.f;
    #pragma unroll
    for (int ic = 0; ic < IND; ++ic) {
        #pragma unroll
        for (int r = 0; r < 3; ++r) {
            float v = s3[r][ic];
            ax += v * w1[(d*IND + ic)*3 + r];
            ac += v * w2[(d*IND + ic)*3 + r];
        }
    }
    g_xA[(b*NN + n)*DIMD + d] = ax;
    g_cA[(b*DIMD + d)*NN + n] = ac;
}

// =================================================================
// init pair state:  c2A = seq2pair(cA)
// =================================================================
__global__ void k_pair0()
{
    int idx = blockIdx.x * blockDim.x + threadIdx.x;
    int j  = idx % NN;
    int r1 = idx / NN;
    int i  = r1 % NN;
    int r2 = r1 / NN;
    int ch = r2 % C2C;
    int b  = r2 / C2C;
    float pv = (ch < DIMD) ? g_cA[(b*DIMD + ch)*NN + i]
                           : g_cA[(b*DIMD + (ch - DIMD))*NN + j];
    g_c2A[idx] = pv;
}

// =================================================================
// c = relu(bn1(conv1d(c, c1d_w[l])))  — chunked smem staging.
// =================================================================
__global__ void __launch_bounds__(384)
k_conv1bn(int rd, const float* __restrict__ w,
          const float* __restrict__ gg, const float* __restrict__ bb)
{
    int d = blockIdx.x;
    int t = threadIdx.x;
    int b = t / NN, n = t % NN;
    const float* c  = rd ? g_cB : g_cA;
    float*       co = rd ? g_cA : g_cB;

    __shared__ float sc[16][2][194];
    __shared__ float wsh[DIMD*3];
    __shared__ float red[2][12];

    wsh[t] = w[d*DIMD*3 + t];
    if (t < 32) { sc[t >> 1][t & 1][0] = 0.f; sc[t >> 1][t & 1][193] = 0.f; }
    __syncthreads();

    float acc = 0.f;
    for (int ec = 0; ec < DIMD; ec += 16) {
        #pragma unroll
        for (int q = 0; q < 16; ++q) {
            int s = q*384 + t;
            int e1 = s / 384;
            int rem = s - e1*384;
            int bb2 = rem / NN, n2 = rem - bb2*NN;
            sc[e1][bb2][n2 + 1] = c[((bb2*DIMD) + ec + e1)*NN + n2];
        }
        __syncthreads();
        #pragma unroll
        for (int e1 = 0; e1 < 16; ++e1) {
            int e = ec + e1;
            acc += sc[e1][b][n]     * wsh[e*3 + 0]
                 + sc[e1][b][n + 1] * wsh[e*3 + 1]
                 + sc[e1][b][n + 2] * wsh[e*3 + 2];
        }
        __syncthreads();
    }

    float s = acc, ss = acc * acc;
    #pragma unroll
    for (int o = 16; o; o >>= 1) {
        s  += __shfl_down_sync(0xffffffffu, s,  o);
        ss += __shfl_down_sync(0xffffffffu, ss, o);
    }
    if (!(t & 31)) { red[0][t >> 5] = s; red[1][t >> 5] = ss; }
    __syncthreads();
    float ts = 0.f, tss = 0.f;
    #pragma unroll
    for (int ww = 0; ww < 12; ++ww) { ts += red[0][ww]; tss += red[1][ww]; }
    float mean = ts * (1.f/384.f);
    float var  = tss * (1.f/384.f) - mean*mean;
    float inv  = rsqrtf(var + 1e-5f);

    float outv = fmaxf((acc - mean) * inv * gg[d] + bb[d], 0.f);
    co[(b*DIMD + d)*NN + n] = outv;
}

// =================================================================
// x = LN(x + c^T)
// =================================================================
__global__ void k_ln(int xs, int cs,
                     const float* __restrict__ gg, const float* __restrict__ bb)
{
    int n = blockIdx.x, b = blockIdx.y, d = threadIdx.x;
    float*       x = xs ? g_xB : g_xA;
    const float* c = cs ? g_cB : g_cA;

    float v = x[(b*NN + n)*DIMD + d] + c[(b*DIMD + d)*NN + n];

    __shared__ float red[2][4];
    float s = v, ss = v*v;
    #pragma unroll
    for (int o = 16; o; o >>= 1) {
        s  += __shfl_down_sync(0xffffffffu, s,  o);
        ss += __shfl_down_sync(0xffffffffu, ss, o);
    }
    if (!(d & 31)) { red[0][d >> 5] = s; red[1][d >> 5] = ss; }
    __syncthreads();
    float m   = (red[0][0]+red[0][1]+red[0][2]+red[0][3]) * (1.f/128.f);
    float var = (red[1][0]+red[1][1]+red[1][2]+red[1][3]) * (1.f/128.f) - m*m;
    float inv = rsqrtf(var + 1e-5f);
    x[(b*NN + n)*DIMD + d] = (v - m) * inv * gg[d] + bb[d];
}

// =================================================================
// split conv2d weights -> bf16 hi/lo, packed pairs along ic.
// grid = 1152 x 256
// =================================================================
__global__ void k_splitw(const float* __restrict__ w)   // w: [256][256][9]
{
    int o = blockIdx.x * 256 + threadIdx.x;
    int oc    = o & 63;
    int p     = (o >> 6) & 7;
    int tap   = (o >> 9) % 9;
    int icc   = (o / 4608) & 15;
    int ocblk = o / 73728;
    int ocg = ocblk*64 + oc;
    int ic0 = icc*16 + 2*p;
    float x0 = w[(ocg*C2C + ic0    )*9 + tap];
    float x1 = w[(ocg*C2C + ic0 + 1)*9 + tap];
    __nv_bfloat16 h0 = __float2bfloat16(x0);
    __nv_bfloat16 h1 = __float2bfloat16(x1);
    __nv_bfloat16 l0 = __float2bfloat16(x0 - __bfloat162float(h0));
    __nv_bfloat16 l1 = __float2bfloat16(x1 - __bfloat162float(h1));
    g_Wh[o] = ((unsigned)__bfloat16_as_ushort(h1) << 16) | __bfloat16_as_ushort(h0);
    g_Wl[o] = ((unsigned)__bfloat16_as_ushort(l1) << 16) | __bfloat16_as_ushort(l0);
}

// =================================================================
// prep conv2d input: v = state + seq2pair(c_cur)
// state = c2A (mode 0) or relu(bn_prev(c2X)) inline (mode 1).
// split bf16 hi/lo, packed (ic even | ic odd<<16) at [b][icpair][row][j].
// grid 36864 x 256
// =================================================================
__global__ void k_prep(int csel, int mode)
{
    int idx = blockIdx.x * 256 + threadIdx.x;      // 0..BPTOT-1
    int j   = idx % NN;
    int r1  = idx / NN;
    int row = r1 % NN;
    int r2  = r1 / NN;
    int icp = r2 % 128;
    int b   = r2 / 128;
    const float* cc = csel ? g_cB : g_cA;

    int ic0 = icp*2, ic1 = ic0 + 1;
    size_t s0 = ((size_t)(b*C2C + ic0)*NN + row)*NN + j;
    size_t s1 = ((size_t)(b*C2C + ic1)*NN + row)*NN + j;
    float st0, st1;
    if (mode) {
        st0 = fmaxf(fmaf(g_c2X[s0], g_scale[ic0], g_shift[ic0]), 0.f);
        st1 = fmaxf(fmaf(g_c2X[s1], g_scale[ic1], g_shift[ic1]), 0.f);
    } else {
        st0 = g_c2A[s0];
        st1 = g_c2A[s1];
    }
    float x0 = st0 + ((ic0 < DIMD) ? cc[(b*DIMD + ic0)*NN + row]
                                   : cc[(b*DIMD + ic0 - DIMD)*NN + j]);
    float x1 = st1 + ((ic1 < DIMD) ? cc[(b*DIMD + ic1)*NN + row]
                                   : cc[(b*DIMD + ic1 - DIMD)*NN + j]);

    __nv_bfloat16 h0 = __float2bfloat16(x0);
    __nv_bfloat16 h1 = __float2bfloat16(x1);
    __nv_bfloat16 l0 = __float2bfloat16(x0 - __bfloat162float(h0));
    __nv_bfloat16 l1 = __float2bfloat16(x1 - __bfloat162float(h1));
    g_Bh[idx] = ((unsigned)__bfloat16_as_ushort(h1) << 16) | __bfloat16_as_ushort(h0);
    g_Bl[idx] = ((unsigned)__bfloat16_as_ushort(l1) << 16) | __bfloat16_as_ushort(l0);
}

// =================================================================
// zero BN accumulators (1 block, 256 threads)
// =================================================================
__global__ void k_zstats()
{
    int t = threadIdx.x;
    g_bnsum[t] = 0.f;
    g_bnsq[t]  = 0.f;
}

// =================================================================
// conv2d 3x3 C2->C2 on tensor cores (bf16 hi/lo split, mma.m16n8k16).
// Input pre-split in g_Bh/g_Bl.  Raw out -> g_c2X.
// Epilogue also accumulates per-oc sum / sumsq into g_bnsum/g_bnsq.
// CTA: 64 oc x output row i x batch.  8 warps: 32 oc x 48 j each.
// =================================================================
#define MMA_BF16(c0,c1,c2,c3, A0,A1,A2,A3, B0,B1)                         \
  asm volatile("mma.sync.aligned.m16n8k16.row.col.f32.bf16.bf16.f32 "     \
    "{%0,%1,%2,%3},{%4,%5,%6,%7},{%8,%9},{%0,%1,%2,%3};"                  \
    : "+f"(c0),"+f"(c1),"+f"(c2),"+f"(c3)                                 \
    : "r"(A0),"r"(A1),"r"(A2),"r"(A3),"r"(B0),"r"(B1))

#define ASZ 5184
#define BSZ 4800
#define CONV_SMEM ((2*ASZ + 2*BSZ)*4)   // 79872 B

__global__ void __launch_bounds__(256, 2)
k_conv2d_mma()
{
    extern __shared__ unsigned smu[];
    unsigned* Ah = smu;
    unsigned* Al = smu + ASZ;
    unsigned* Bh = smu + 2*ASZ;
    unsigned* Bl = smu + 2*ASZ + BSZ;
    __shared__ float sS[64], sQ[64];

    int ocblk = blockIdx.x;       // 0..3
    int i     = blockIdx.y;       // 0..191
    int b     = blockIdx.z;       // 0..1
    int t = threadIdx.x;
    int w = t >> 5, lane = t & 31;
    int g = lane >> 2, tig = lane & 3;
    int wm = w & 1, wn = w >> 1;

    // zero B halo columns + stats accumulators (written once)
    if (t < 192) {
        int rr = t / 8, cq = t & 7;
        int col = (cq < 4) ? cq : (192 + cq);
        Bh[rr*200 + col] = 0u;
        Bl[rr*200 + col] = 0u;
    }
    if (t < 64) { sS[t] = 0.f; sQ[t] = 0.f; }

    float acc[2][6][4];
    #pragma unroll
    for (int m = 0; m < 2; ++m)
        #pragma unroll
        for (int u = 0; u < 6; ++u)
            #pragma unroll
            for (int q = 0; q < 4; ++q) acc[m][u][q] = 0.f;

    const unsigned* whsrc = g_Wh + ocblk*73728;
    const unsigned* wlsrc = g_Wl + ocblk*73728;

    for (int icc = 0; icc < 16; ++icc) {
        // ---- stage weights: 2 x 1152 uint4 ----
        #pragma unroll
        for (int q = 0; q < 9; ++q) {
            int sidx = q*256 + t;
            int hl = sidx >= 1152;
            int s2 = hl ? sidx - 1152 : sidx;
            int s4 = s2 * 4;
            int tap = s4 >> 9, p = (s4 >> 6) & 7, oc = s4 & 63;
            int dst = ((tap*8 + p)*72 + oc) >> 2;
            const uint4 v = ((const uint4*)(hl ? wlsrc : whsrc))[icc*1152 + s2];
            ((uint4*)(hl ? Al : Ah))[dst] = v;
        }
        // ---- stage input: 2 x 24 segs x 48 uint4 ----
        #pragma unroll
        for (int q = 0; q < 9; ++q) {
            int sidx = q*256 + t;
            int hl = sidx >= 1152;
            int s2 = hl ? sidx - 1152 : sidx;
            int seg = s2 / 48, v4 = s2 - seg*48;   // seg = r*8+icp
            int r = seg >> 3, icp = seg & 7;
            int row = i - 1 + r;
            uint4 val = make_uint4(0u,0u,0u,0u);
            if (row >= 0 && row < NN)
                val = ((const uint4*)(hl ? g_Bl : g_Bh))
                        [(size_t)((b*128 + icc*8 + icp)*NN + row)*48 + v4];
            ((uint4*)(hl ? Bl : Bh))[(seg*200 + 4 + v4*4) >> 2] = val;
        }
        __syncthreads();

        #pragma unroll
        for (int r = 0; r < 3; ++r) {
            #pragma unroll
            for (int dj = 0; dj < 3; ++dj) {
                int tap = r*3 + dj;
                unsigned ah[2][4], al[2][4];
                #pragma unroll
                for (int m = 0; m < 2; ++m) {
                    int mb = wm*32 + m*16 + g;
                    ah[m][0] = Ah[(tap*8 + tig    )*72 + mb    ];
                    ah[m][1] = Ah[(tap*8 + tig    )*72 + mb + 8];
                    ah[m][2] = Ah[(tap*8 + tig + 4)*72 + mb    ];
                    ah[m][3] = Ah[(tap*8 + tig + 4)*72 + mb + 8];
                    al[m][0] = Al[(tap*8 + tig    )*72 + mb    ];
                    al[m][1] = Al[(tap*8 + tig    )*72 + mb + 8];
                    al[m][2] = Al[(tap*8 + tig + 4)*72 + mb    ];
                    al[m][3] = Al[(tap*8 + tig + 4)*72 + mb + 8];
                }
                #pragma unroll
                for (int u = 0; u < 6; ++u) {
                    int col = wn*48 + u*8 + g + dj + 3;
                    unsigned bh0 = Bh[(r*8 + tig    )*200 + col];
                    unsigned bh1 = Bh[(r*8 + tig + 4)*200 + col];
                    unsigned bl0 = Bl[(r*8 + tig    )*200 + col];
                    unsigned bl1 = Bl[(r*8 + tig + 4)*200 + col];
                    #pragma unroll
                    for (int m = 0; m < 2; ++m) {
                        float* c = acc[m][u];
                        MMA_BF16(c[0],c[1],c[2],c[3],
                                 ah[m][0],ah[m][1],ah[m][2],ah[m][3], bh0,bh1);
                        MMA_BF16(c[0],c[1],c[2],c[3],
                                 ah[m][0],ah[m][1],ah[m][2],ah[m][3], bl0,bl1);
                        MMA_BF16(c[0],c[1],c[2],c[3],
                                 al[m][0],al[m][1],al[m][2],al[m][3], bh0,bh1);
                    }
                }
            }
        }
        __syncthreads();
    }

    // ---- epilogue: write raw conv output + per-oc stats partials ----
    #pragma unroll
    for (int m = 0; m < 2; ++m) {
        int oc0 = ocblk*64 + wm*32 + m*16 + g;
        float s0 = 0.f, q0 = 0.f, s1 = 0.f, q1 = 0.f;
        #pragma unroll
        for (int u = 0; u < 6; ++u) {
            int j = wn*48 + u*8 + 2*tig;
            float a0 = acc[m][u][0], a1 = acc[m][u][1];
            float a2 = acc[m][u][2], a3 = acc[m][u][3];
            s0 += a0 + a1;  q0 += a0*a0 + a1*a1;
            s1 += a2 + a3;  q1 += a2*a2 + a3*a3;
            *(float2*)&g_c2X[((size_t)(b*C2C + oc0    )*NN + i)*NN + j] = make_float2(a0, a1);
            *(float2*)&g_c2X[((size_t)(b*C2C + oc0 + 8)*NN + i)*NN + j] = make_float2(a2, a3);
        }
        // quad reduce over tig (lanes g*4 + tig)
        s0 += __shfl_down_sync(0xffffffffu, s0, 2);
        s0 += __shfl_down_sync(0xffffffffu, s0, 1);
        q0 += __shfl_down_sync(0xffffffffu, q0, 2);
        q0 += __shfl_down_sync(0xffffffffu, q0, 1);
        s1 += __shfl_down_sync(0xffffffffu, s1, 2);
        s1 += __shfl_down_sync(0xffffffffu, s1, 1);
        q1 += __shfl_down_sync(0xffffffffu, q1, 2);
        q1 += __shfl_down_sync(0xffffffffu, q1, 1);
        if (tig == 0) {
            int lo = wm*32 + m*16 + g;
            atomicAdd(&sS[lo    ], s0);
            atomicAdd(&sQ[lo    ], q0);
            atomicAdd(&sS[lo + 8], s1);
            atomicAdd(&sQ[lo + 8], q1);
        }
    }
    __syncthreads();
    if (t < 64) {
        atomicAdd(&g_bnsum[ocblk*64 + t], sS[t]);
        atomicAdd(&g_bnsq [ocblk*64 + t], sQ[t]);
    }
}

// =================================================================
// BN finalize: per-oc scale/shift from accumulated sums (1 block, 256 thr)
// =================================================================
__global__ void k_bnfin(const float* __restrict__ gg, const float* __restrict__ bb)
{
    int oc = threadIdx.x;
    float mean = g_bnsum[oc] * (1.f / (NB*NSP));
    float var  = g_bnsq[oc] * (1.f / (NB*NSP)) - mean*mean;
    float inv  = rsqrtf(var + 1e-5f);
    float sc = inv * gg[oc];
    g_scale[oc] = sc;
    g_shift[oc] = bb[oc] - mean * sc;
}

// =================================================================
// gate logits with BN+relu applied inline from raw c2X
// =================================================================
__global__ void k_gate(const float* __restrict__ wd)
{
    int i = blockIdx.x, b = blockIdx.y, j = threadIdx.x;
    __shared__ float wsh[C2C*HH];
    __shared__ float scs[C2C], shs[C2C];
    for (int s = j; s < C2C*HH; s += NN) {
        int c = s >> 3, h = s & 7;
        wsh[s] = wd[h*C2C + c];
    }
    for (int s = j; s < C2C; s += NN) { scs[s] = g_scale[s]; shs[s] = g_shift[s]; }
    __syncthreads();
    float acc[HH] = {};
    const float* base = g_c2X + (size_t)(b*C2C)*NSP + i*NN + j;
    #pragma unroll 4
    for (int c = 0; c < C2C; ++c) {
        float v = fmaxf(fmaf(base[(size_t)c*NSP], scs[c], shs[c]), 0.f);
        #pragma unroll
        for (int h = 0; h < HH; ++h) acc[h] += v * wsh[c*8 + h];
    }
    #pragma unroll
    for (int h = 0; h < HH; ++h)
        g_G[((b*HH + h)*NN + i)*NN + j] = acc[h];
}

// =================================================================
// Generic 384x128x128 GEMM with relu epilogue.
// =================================================================
__global__ void k_gemm64(int asel, int addupd,
                         const float* __restrict__ W,
                         const float* __restrict__ bias,
                         int outsel, float* dptr)
{
    __shared__ float As[32*68];
    __shared__ float Ws[32*68];
    int t = threadIdx.x;
    int tx = t & 15, ty = t >> 4;
    int rowbase = blockIdx.y * 64, colbase = blockIdx.x * 64;

    const float* A = asel ? g_xB : g_xA;
    float* outp;
    if      (outsel == 3) { outp = g_xA; }
    else if (outsel == 4) { outp = g_xB; }
    else                  { outp = dptr; }

    float acc[4][4] = {};
    for (int kk = 0; kk < 128; kk += 32) {
        #pragma unroll
        for (int r = 0; r < 8; ++r) {
            int s = r*256 + t;
            int row = s >> 5, e = s & 31;
            float v = A[(rowbase + row)*DIMD + kk + e];
            if (addupd) v += g_upd[(rowbase + row)*DIMD + kk + e];
            As[e*68 + row] = v;
            Ws[e*68 + row] = W[(colbase + row)*DIMD + kk + e];
        }
        __syncthreads();
        #pragma unroll
        for (int e = 0; e < 32; ++e) {
            float a0 = As[e*68 + ty*4 + 0], a1 = As[e*68 + ty*4 + 1];
            float a2 = As[e*68 + ty*4 + 2], a3 = As[e*68 + ty*4 + 3];
            float w0 = Ws[e*68 + tx*4 + 0], w1 = Ws[e*68 + tx*4 + 1];
            float w2 = Ws[e*68 + tx*4 + 2], w3 = Ws[e*68 + tx*4 + 3];
            acc[0][0] += a0*w0; acc[0][1] += a0*w1; acc[0][2] += a0*w2; acc[0][3] += a0*w3;
            acc[1][0] += a1*w0; acc[1][1] += a1*w1; acc[1][2] += a1*w2; acc[1][3] += a1*w3;
            acc[2][0] += a2*w0; acc[2][1] += a2*w1; acc[2][2] += a2*w2; acc[2][3] += a2*w3;
            acc[3][0] += a3*w0; acc[3][1] += a3*w1; acc[3][2] += a3*w2; acc[3][3] += a3*w3;
        }
        __syncthreads();
    }

    #pragma unroll
    for (int v = 0; v < 4; ++v) {
        int row = rowbase + ty*4 + v;
        #pragma unroll
        for (int u = 0; u < 4; ++u) {
            int col = colbase + tx*4 + u;
            float r = fmaxf(acc[v][u] + bias[col], 0.f);
            outp[row*DIMD + col] = r;
        }
    }
}

// =================================================================
// fused q/k/v GEMM: one launch, 3 weight sets; grid (6, 6).
// blockIdx.x: sel = x>>1 (0=q,1=k,2=v), colbase = (x&1)*64.
// =================================================================
__global__ void k_gemm_qkv(int asel,
                           const float* __restrict__ Wq, const float* __restrict__ bq,
                           const float* __restrict__ Wk, const float* __restrict__ bk,
                           const float* __restrict__ Wv, const float* __restrict__ bv)
{
    __shared__ float As[32*68];
    __shared__ float Ws[32*68];
    int t = threadIdx.x;
    int tx = t & 15, ty = t >> 4;
    int sel = blockIdx.x >> 1;
    int rowbase = blockIdx.y * 64, colbase = (blockIdx.x & 1) * 64;

    const float* A = asel ? g_xB : g_xA;
    const float* W    = (sel == 0) ? Wq : (sel == 1) ? Wk : Wv;
    const float* bias = (sel == 0) ? bq : (sel == 1) ? bk : bv;
    float* outp       = (sel == 0) ? g_q : (sel == 1) ? g_k : g_v;

    float acc[4][4] = {};
    for (int kk = 0; kk < 128; kk += 32) {
        #pragma unroll
        for (int r = 0; r < 8; ++r) {
            int s = r*256 + t;
            int row = s >> 5, e = s & 31;
            As[e*68 + row] = A[(rowbase + row)*DIMD + kk + e];
            Ws[e*68 + row] = W[(colbase + row)*DIMD + kk + e];
        }
        __syncthreads();
        #pragma unroll
        for (int e = 0; e < 32; ++e) {
            float a0 = As[e*68 + ty*4 + 0], a1 = As[e*68 + ty*4 + 1];
            float a2 = As[e*68 + ty*4 + 2], a3 = As[e*68 + ty*4 + 3];
            float w0 = Ws[e*68 + tx*4 + 0], w1 = Ws[e*68 + tx*4 + 1];
            float w2 = Ws[e*68 + tx*4 + 2], w3 = Ws[e*68 + tx*4 + 3];
            acc[0][0] += a0*w0; acc[0][1] += a0*w1; acc[0][2] += a0*w2; acc[0][3] += a0*w3;
            acc[1][0] += a1*w0; acc[1][1] += a1*w1; acc[1][2] += a1*w2; acc[1][3] += a1*w3;
            acc[2][0] += a2*w0; acc[2][1] += a2*w1; acc[2][2] += a2*w2; acc[2][3] += a2*w3;
            acc[3][0] += a3*w0; acc[3][1] += a3*w1; acc[3][2] += a3*w2; acc[3][3] += a3*w3;
        }
        __syncthreads();
    }

    #pragma unroll
    for (int v = 0; v < 4; ++v) {
        int row = rowbase + ty*4 + v;
        #pragma unroll
        for (int u = 0; u < 4; ++u) {
            int col = colbase + tx*4 + u;
            float r = fmaxf(acc[v][u] + bias[col], 0.f);
            int b = row / NN, n = row % NN, h = col >> 4, dh = col & 15;
            outp[((b*HH + h)*NN + n)*DHH + dh] = r;
        }
    }
}

// =================================================================
// Attention + gate
// =================================================================
__global__ void k_attn(const float* __restrict__ mask,
                       const float* __restrict__ wdb)
{
    int i = blockIdx.x, h = blockIdx.y, b = blockIdx.z;
    int t = threadIdx.x;
    int bh = b*HH + h;

    __shared__ float qi[DHH];
    __shared__ float att[NN];
    __shared__ float redm[8];
    __shared__ float reds[8];
    __shared__ float part[16][17];

    if (t < DHH) qi[t] = g_q[(bh*NN + i)*DHH + t];
    __syncthreads();

    float aval = 0.f;
    if (t < NN) {
        const float* kp = g_k + (bh*NN + t)*DHH;
        float s = 0.f;
        #pragma unroll
        for (int d = 0; d < DHH; ++d) s += qi[d] * kp[d];
        aval = s * 0.25f;
    }
    float mval = (t < NN) ? aval : -3e38f;
    #pragma unroll
    for (int o = 16; o; o >>= 1) mval = fmaxf(mval, __shfl_xor_sync(0xffffffffu, mval, o));
    if (!(t & 31)) redm[t >> 5] = mval;
    __syncthreads();
    float mx = redm[0];
    #pragma unroll
    for (int ww = 1; ww < 8; ++ww) mx = fmaxf(mx, redm[ww]);

    float e = (t < NN) ? expf(aval - mx) * mask[b*NN + t] : 0.f;
    float sv = e;
    #pragma unroll
    for (int o = 16; o; o >>= 1) sv += __shfl_xor_sync(0xffffffffu, sv, o);
    if (!(t & 31)) reds[t >> 5] = sv;
    __syncthreads();
    float den = 1e-6f;
    #pragma unroll
    for (int ww = 0; ww < 8; ++ww) den += reds[ww];

    if (t < NN) {
        float gl = g_G[(bh*NN + i)*NN + t] + g_G[(bh*NN + t)*NN + i] + wdb[h];
        float gate = 1.f / (1.f + expf(-gl));
        att[t] = (e / den) * gate;
    }
    __syncthreads();

    int d = t & 15, grp = t >> 4;
    float p = 0.f;
    #pragma unroll
    for (int jj = 0; jj < 12; ++jj) {
        int j = grp*12 + jj;
        p += att[j] * g_v[(bh*NN + j)*DHH + d];
    }
    part[grp][d] = p;
    __syncthreads();
    if (t < DHH) {
        float s = 0.f;
        #pragma unroll
        for (int gg = 0; gg < 16; ++gg) s += part[gg][t];
        g_upd[(b*NN + i)*DIMD + h*DHH + t] = s;
    }
}

// =================================================================
// host
// =================================================================
extern "C" void kernel_launch(void* const* d_in, const int* in_sizes, int n_in,
                              void* d_out, int out_size)
{
    const float* seq     = (const float*)d_in[0];
    const float* mask    = (const float*)d_in[1];
    const float* conv1_w = (const float*)d_in[2];
    const float* conv2_w = (const float*)d_in[3];
    const float* ln_g    = (const float*)d_in[4];
    const float* ln_b    = (const float*)d_in[5];
    const float* c1d_w   = (const float*)d_in[6];
    const float* bn1_g   = (const float*)d_in[7];
    const float* bn1_b   = (const float*)d_in[8];
    const float* c2d_w   = (const float*)d_in[9];
    const float* bn2_g   = (const float*)d_in[10];
    const float* bn2_b   = (const float*)d_in[11];
    const float* wq_w    = (const float*)d_in[12];
    const float* wq_b    = (const float*)d_in[13];
    const float* wk_w    = (const float*)d_in[14];
    const float* wk_b    = (const float*)d_in[15];
    const float* wv_w    = (const float*)d_in[16];
    const float* wv_b    = (const float*)d_in[17];
    const float* wd_w    = (const float*)d_in[18];
    const float* wd_b    = (const float*)d_in[19];
    const float* wl_w    = (const float*)d_in[20];
    const float* wl_b    = (const float*)d_in[21];
    const float* fc_w    = (const float*)d_in[22];
    const float* fc_b    = (const float*)d_in[23];
    float* out = (float*)d_out;

    static int smem_set = 0;
    if (!smem_set) {
        cudaFuncSetAttribute(k_conv2d_mma, cudaFuncAttributeMaxDynamicSharedMemorySize, CONV_SMEM);
        smem_set = 1;
    }

    k_stem<<<dim3(NN, NB), 128>>>(seq, conv1_w, conv2_w);
    k_pair0<<<C2TOT/256, 256>>>();

    int xs = 0;
    for (int l = 0; l < 3; ++l) {
        int rd   = l & 1;        // which buffer holds incoming c
        int cnew = rd ^ 1;       // buffer that will hold new c

        k_conv1bn<<<DIMD, 384>>>(rd, c1d_w + l*DIMD*DIMD*3, bn1_g + l*DIMD, bn1_b + l*DIMD);
        k_ln<<<dim3(NN, NB), DIMD>>>(xs, cnew, ln_g + l*DIMD, ln_b + l*DIMD);
        k_splitw<<<1152, 256>>>(c2d_w + l*C2C*C2C*9);
        k_prep<<<BPTOT/256, 256>>>(cnew, l > 0 ? 1 : 0);
        k_zstats<<<1, 256>>>();
        k_conv2d_mma<<<dim3(4, NN, NB), 256, CONV_SMEM>>>();
        k_bnfin<<<1, 256>>>(bn2_g + l*C2C, bn2_b + l*C2C);
        k_gate<<<dim3(NN, NB), NN>>>(wd_w + l*HH*C2C);
        k_gemm_qkv<<<dim3(6, 6), 256>>>(xs, wq_w + l*DIMD*DIMD, wq_b + l*DIMD,
                                            wk_w + l*DIMD*DIMD, wk_b + l*DIMD,
                                            wv_w + l*DIMD*DIMD, wv_b + l*DIMD);
        k_attn<<<dim3(NN, HH, NB), 256>>>(mask, wd_b + l*HH);
        k_gemm64<<<dim3(2, 6), 256>>>(xs, 1, wl_w + l*DIMD*DIMD, wl_b + l*DIMD, xs ? 3 : 4, nullptr);
        xs ^= 1;
    }
    k_gemm64<<<dim3(2, 6), 256>>>(xs, 0, fc_w, fc_b, 5, out);
}

// round 14
// speedup vs baseline: 3.2143x; 1.2421x over previous
#include <cuda_runtime.h>
#include <cuda_fp16.h>
#include <cstdint>

// ---------------- problem constants ----------------
#define NB   2
#define NN   192
#define IND  20
#define DIMD 128
#define HH   8
#define DHH  16
#define C2C  256
#define NSP  (NN*NN)            // 36864
#define C2TOT (NB*C2C*NSP)      // 18874368

// ---------------- scratch (device globals; no allocation allowed) ----------------
__device__ float g_xA[NB*NN*DIMD];
__device__ float g_xB[NB*NN*DIMD];
__device__ float g_cA[NB*DIMD*NN];
__device__ float g_cB[NB*DIMD*NN];
__device__ float g_q[NB*HH*NN*DHH];
__device__ float g_k[NB*HH*NN*DHH];
__device__ float g_v[NB*HH*NN*DHH];
__device__ float g_upd[NB*NN*DIMD];
__device__ float g_G[NB*HH*NSP];
__device__ float g_scale[C2C];
__device__ float g_shift[C2C];
__device__ float g_bnsum[C2C];
__device__ float g_bnsq[C2C];
__device__ float g_c2A[C2TOT];     // layer-0 initial pair state only
__device__ float g_c2X[C2TOT];     // raw conv2d output (pre-BN)
// fp16 conv weights packed (ic even | ic odd<<16): [ocblk4][icc16][tap9][icpair8][oc64]
__device__ unsigned g_Wq[C2C*C2C*9/2];
// fp16 hi/lo split conv input packed by ic-pair: [b2][icpair128][row192][j192]
#define BPTOT (NB*128*NN*NN)    // 9437184
__device__ unsigned g_Bh[BPTOT];
__device__ unsigned g_Bl[BPTOT];

// =================================================================
// Stem: x = conv1d(seq^T, conv1_w)^T ; c = conv1d(seq^T, conv2_w)
// =================================================================
__global__ void k_stem(const float* __restrict__ seq,
                       const float* __restrict__ w1,
                       const float* __restrict__ w2)
{
    int n = blockIdx.x, b = blockIdx.y, d = threadIdx.x;
    __shared__ float s3[3][IND];
    if (d < 3*IND) {
        int r = d / IND, ic = d % IND;
        int nn = n - 1 + r;
        s3[r][ic] = (nn >= 0 && nn < NN) ? seq[(b*NN + nn)*IND + ic] : 0.f;
    }
    __syncthreads();
    float ax = 0.f, ac = 0.f;
    #pragma unroll
    for (int ic = 0; ic < IND; ++ic) {
        #pragma unroll
        for (int r = 0; r < 3; ++r) {
            float v = s3[r][ic];
            ax += v * w1[(d*IND + ic)*3 + r];
            ac += v * w2[(d*IND + ic)*3 + r];
        }
    }
    g_xA[(b*NN + n)*DIMD + d] = ax;
    g_cA[(b*DIMD + d)*NN + n] = ac;
}

// =================================================================
// init pair state:  c2A = seq2pair(cA)
// =================================================================
__global__ void k_pair0()
{
    int idx = blockIdx.x * blockDim.x + threadIdx.x;
    int j  = idx % NN;
    int r1 = idx / NN;
    int i  = r1 % NN;
    int r2 = r1 / NN;
    int ch = r2 % C2C;
    int b  = r2 / C2C;
    float pv = (ch < DIMD) ? g_cA[(b*DIMD + ch)*NN + i]
                           : g_cA[(b*DIMD + (ch - DIMD))*NN + j];
    g_c2A[idx] = pv;
}

// =================================================================
// c = relu(bn1(conv1d(c, c1d_w[l])))  — chunked smem staging.
// =================================================================
__global__ void __launch_bounds__(384)
k_conv1bn(int rd, const float* __restrict__ w,
          const float* __restrict__ gg, const float* __restrict__ bb)
{
    int d = blockIdx.x;
    int t = threadIdx.x;
    int b = t / NN, n = t % NN;
    const float* c  = rd ? g_cB : g_cA;
    float*       co = rd ? g_cA : g_cB;

    __shared__ float sc[16][2][194];
    __shared__ float wsh[DIMD*3];
    __shared__ float red[2][12];

    wsh[t] = w[d*DIMD*3 + t];
    if (t < 32) { sc[t >> 1][t & 1][0] = 0.f; sc[t >> 1][t & 1][193] = 0.f; }
    __syncthreads();

    float acc = 0.f;
    for (int ec = 0; ec < DIMD; ec += 16) {
        #pragma unroll
        for (int q = 0; q < 16; ++q) {
            int s = q*384 + t;
            int e1 = s / 384;
            int rem = s - e1*384;
            int bb2 = rem / NN, n2 = rem - bb2*NN;
            sc[e1][bb2][n2 + 1] = c[((bb2*DIMD) + ec + e1)*NN + n2];
        }
        __syncthreads();
        #pragma unroll
        for (int e1 = 0; e1 < 16; ++e1) {
            int e = ec + e1;
            acc += sc[e1][b][n]     * wsh[e*3 + 0]
                 + sc[e1][b][n + 1] * wsh[e*3 + 1]
                 + sc[e1][b][n + 2] * wsh[e*3 + 2];
        }
        __syncthreads();
    }

    float s = acc, ss = acc * acc;
    #pragma unroll
    for (int o = 16; o; o >>= 1) {
        s  += __shfl_down_sync(0xffffffffu, s,  o);
        ss += __shfl_down_sync(0xffffffffu, ss, o);
    }
    if (!(t & 31)) { red[0][t >> 5] = s; red[1][t >> 5] = ss; }
    __syncthreads();
    float ts = 0.f, tss = 0.f;
    #pragma unroll
    for (int ww = 0; ww < 12; ++ww) { ts += red[0][ww]; tss += red[1][ww]; }
    float mean = ts * (1.f/384.f);
    float var  = tss * (1.f/384.f) - mean*mean;
    float inv  = rsqrtf(var + 1e-5f);

    float outv = fmaxf((acc - mean) * inv * gg[d] + bb[d], 0.f);
    co[(b*DIMD + d)*NN + n] = outv;
}

// =================================================================
// x = LN(x + c^T)
// =================================================================
__global__ void k_ln(int xs, int cs,
                     const float* __restrict__ gg, const float* __restrict__ bb)
{
    int n = blockIdx.x, b = blockIdx.y, d = threadIdx.x;
    float*       x = xs ? g_xB : g_xA;
    const float* c = cs ? g_cB : g_cA;

    float v = x[(b*NN + n)*DIMD + d] + c[(b*DIMD + d)*NN + n];

    __shared__ float red[2][4];
    float s = v, ss = v*v;
    #pragma unroll
    for (int o = 16; o; o >>= 1) {
        s  += __shfl_down_sync(0xffffffffu, s,  o);
        ss += __shfl_down_sync(0xffffffffu, ss, o);
    }
    if (!(d & 31)) { red[0][d >> 5] = s; red[1][d >> 5] = ss; }
    __syncthreads();
    float m   = (red[0][0]+red[0][1]+red[0][2]+red[0][3]) * (1.f/128.f);
    float var = (red[1][0]+red[1][1]+red[1][2]+red[1][3]) * (1.f/128.f) - m*m;
    float inv = rsqrtf(var + 1e-5f);
    x[(b*NN + n)*DIMD + d] = (v - m) * inv * gg[d] + bb[d];
}

// =================================================================
// conv2d weights -> single fp16, packed pairs along ic; also zeros BN accum.
// grid = 1152 x 256 (294912 u32)
// =================================================================
__global__ void k_splitw(const float* __restrict__ w)   // w: [256][256][9]
{
    int o = blockIdx.x * 256 + threadIdx.x;
    int oc    = o & 63;
    int p     = (o >> 6) & 7;
    int tap   = (o >> 9) % 9;
    int icc   = (o / 4608) & 15;
    int ocblk = o / 73728;
    int ocg = ocblk*64 + oc;
    int ic0 = icc*16 + 2*p;
    __half h0 = __float2half(w[(ocg*C2C + ic0    )*9 + tap]);
    __half h1 = __float2half(w[(ocg*C2C + ic0 + 1)*9 + tap]);
    g_Wq[o] = ((unsigned)__half_as_ushort(h1) << 16) | __half_as_ushort(h0);
    if (o < C2C) { g_bnsum[o] = 0.f; g_bnsq[o] = 0.f; }
}

// =================================================================
// prep conv2d input: v = state + seq2pair(c_cur)
// state = c2A (mode 0) or relu(bn_prev(c2X)) inline (mode 1).
// split fp16 hi/lo, packed (ic even | ic odd<<16) at [b][icpair][row][j].
// grid 36864 x 256
// =================================================================
__global__ void k_prep(int csel, int mode)
{
    int idx = blockIdx.x * 256 + threadIdx.x;      // 0..BPTOT-1
    int j   = idx % NN;
    int r1  = idx / NN;
    int row = r1 % NN;
    int r2  = r1 / NN;
    int icp = r2 % 128;
    int b   = r2 / 128;
    const float* cc = csel ? g_cB : g_cA;

    int ic0 = icp*2, ic1 = ic0 + 1;
    size_t s0 = ((size_t)(b*C2C + ic0)*NN + row)*NN + j;
    size_t s1 = ((size_t)(b*C2C + ic1)*NN + row)*NN + j;
    float st0, st1;
    if (mode) {
        st0 = fmaxf(fmaf(g_c2X[s0], g_scale[ic0], g_shift[ic0]), 0.f);
        st1 = fmaxf(fmaf(g_c2X[s1], g_scale[ic1], g_shift[ic1]), 0.f);
    } else {
        st0 = g_c2A[s0];
        st1 = g_c2A[s1];
    }
    float x0 = st0 + ((ic0 < DIMD) ? cc[(b*DIMD + ic0)*NN + row]
                                   : cc[(b*DIMD + ic0 - DIMD)*NN + j]);
    float x1 = st1 + ((ic1 < DIMD) ? cc[(b*DIMD + ic1)*NN + row]
                                   : cc[(b*DIMD + ic1 - DIMD)*NN + j]);

    __half h0 = __float2half(x0);
    __half h1 = __float2half(x1);
    __half l0 = __float2half(x0 - __half2float(h0));
    __half l1 = __float2half(x1 - __half2float(h1));
    g_Bh[idx] = ((unsigned)__half_as_ushort(h1) << 16) | __half_as_ushort(h0);
    g_Bl[idx] = ((unsigned)__half_as_ushort(l1) << 16) | __half_as_ushort(l0);
}

// =================================================================
// conv2d 3x3 C2->C2 on tensor cores (fp16 2-term: W*(bh+bl), mma.m16n8k16).
// Input pre-split in g_Bh/g_Bl, fp16 weights in g_Wq.  Raw out -> g_c2X.
// Epilogue accumulates per-oc sum/sumsq into g_bnsum/g_bnsq.
// CTA: 64 oc x output row i x batch.  8 warps: 32 oc x 48 j each.
// Smem (u32): Aq [tap9][icpair8][oc stride 72]  (5184)
//             Bh/Bl [r3*icpair8][col stride 200] (4800 each), data at col 4..195
// =================================================================
#define MMA_F16(c0,c1,c2,c3, A0,A1,A2,A3, B0,B1)                          \
  asm volatile("mma.sync.aligned.m16n8k16.row.col.f32.f16.f16.f32 "       \
    "{%0,%1,%2,%3},{%4,%5,%6,%7},{%8,%9},{%0,%1,%2,%3};"                  \
    : "+f"(c0),"+f"(c1),"+f"(c2),"+f"(c3)                                 \
    : "r"(A0),"r"(A1),"r"(A2),"r"(A3),"r"(B0),"r"(B1))

#define ASZ 5184
#define BSZ 4800
#define CONV_SMEM ((ASZ + 2*BSZ)*4)   // 59136 B

__global__ void __launch_bounds__(256, 2)
k_conv2d_mma()
{
    extern __shared__ unsigned smu[];
    unsigned* Aq = smu;
    unsigned* Bh = smu + ASZ;
    unsigned* Bl = smu + ASZ + BSZ;
    __shared__ float sS[64], sQ[64];

    int ocblk = blockIdx.x;       // 0..3
    int i     = blockIdx.y;       // 0..191
    int b     = blockIdx.z;       // 0..1
    int t = threadIdx.x;
    int w = t >> 5, lane = t & 31;
    int g = lane >> 2, tig = lane & 3;
    int wm = w & 1, wn = w >> 1;

    // zero B halo columns + stats accumulators (written once)
    if (t < 192) {
        int rr = t / 8, cq = t & 7;
        int col = (cq < 4) ? cq : (192 + cq);
        Bh[rr*200 + col] = 0u;
        Bl[rr*200 + col] = 0u;
    }
    if (t < 64) { sS[t] = 0.f; sQ[t] = 0.f; }

    float acc[2][6][4];
    #pragma unroll
    for (int m = 0; m < 2; ++m)
        #pragma unroll
        for (int u = 0; u < 6; ++u)
            #pragma unroll
            for (int q = 0; q < 4; ++q) acc[m][u][q] = 0.f;

    const unsigned* wsrc = g_Wq + ocblk*73728;

    for (int icc = 0; icc < 16; ++icc) {
        // ---- stage weights: 1152 uint4 ----
        for (int s2 = t; s2 < 1152; s2 += 256) {
            int s4 = s2 * 4;
            int tap = s4 >> 9, p = (s4 >> 6) & 7, oc = s4 & 63;
            ((uint4*)Aq)[((tap*8 + p)*72 + oc) >> 2] =
                ((const uint4*)wsrc)[icc*1152 + s2];
        }
        // ---- stage input: 2 x 24 segs x 48 uint4 ----
        #pragma unroll
        for (int q = 0; q < 9; ++q) {
            int sidx = q*256 + t;
            int hl = sidx >= 1152;
            int s2 = hl ? sidx - 1152 : sidx;
            int seg = s2 / 48, v4 = s2 - seg*48;   // seg = r*8+icp
            int r = seg >> 3, icp = seg & 7;
            int row = i - 1 + r;
            uint4 val = make_uint4(0u,0u,0u,0u);
            if (row >= 0 && row < NN)
                val = ((const uint4*)(hl ? g_Bl : g_Bh))
                        [(size_t)((b*128 + icc*8 + icp)*NN + row)*48 + v4];
            ((uint4*)(hl ? Bl : Bh))[(seg*200 + 4 + v4*4) >> 2] = val;
        }
        __syncthreads();

        #pragma unroll
        for (int r = 0; r < 3; ++r) {
            #pragma unroll
            for (int dj = 0; dj < 3; ++dj) {
                int tap = r*3 + dj;
                unsigned aq[2][4];
                #pragma unroll
                for (int m = 0; m < 2; ++m) {
                    int mb = wm*32 + m*16 + g;
                    aq[m][0] = Aq[(tap*8 + tig    )*72 + mb    ];
                    aq[m][1] = Aq[(tap*8 + tig    )*72 + mb + 8];
                    aq[m][2] = Aq[(tap*8 + tig + 4)*72 + mb    ];
                    aq[m][3] = Aq[(tap*8 + tig + 4)*72 + mb + 8];
                }
                #pragma unroll
                for (int u = 0; u < 6; ++u) {
                    int col = wn*48 + u*8 + g + dj + 3;
                    unsigned bh0 = Bh[(r*8 + tig    )*200 + col];
                    unsigned bh1 = Bh[(r*8 + tig + 4)*200 + col];
                    unsigned bl0 = Bl[(r*8 + tig    )*200 + col];
                    unsigned bl1 = Bl[(r*8 + tig + 4)*200 + col];
                    #pragma unroll
                    for (int m = 0; m < 2; ++m) {
                        float* c = acc[m][u];
                        MMA_F16(c[0],c[1],c[2],c[3],
                                aq[m][0],aq[m][1],aq[m][2],aq[m][3], bh0,bh1);
                        MMA_F16(c[0],c[1],c[2],c[3],
                                aq[m][0],aq[m][1],aq[m][2],aq[m][3], bl0,bl1);
                    }
                }
            }
        }
        __syncthreads();
    }

    // ---- epilogue: write raw conv output + per-oc stats partials ----
    #pragma unroll
    for (int m = 0; m < 2; ++m) {
        int oc0 = ocblk*64 + wm*32 + m*16 + g;
        float s0 = 0.f, q0 = 0.f, s1 = 0.f, q1 = 0.f;
        #pragma unroll
        for (int u = 0; u < 6; ++u) {
            int j = wn*48 + u*8 + 2*tig;
            float a0 = acc[m][u][0], a1 = acc[m][u][1];
            float a2 = acc[m][u][2], a3 = acc[m][u][3];
            s0 += a0 + a1;  q0 += a0*a0 + a1*a1;
            s1 += a2 + a3;  q1 += a2*a2 + a3*a3;
            *(float2*)&g_c2X[((size_t)(b*C2C + oc0    )*NN + i)*NN + j] = make_float2(a0, a1);
            *(float2*)&g_c2X[((size_t)(b*C2C + oc0 + 8)*NN + i)*NN + j] = make_float2(a2, a3);
        }
        s0 += __shfl_down_sync(0xffffffffu, s0, 2);
        s0 += __shfl_down_sync(0xffffffffu, s0, 1);
        q0 += __shfl_down_sync(0xffffffffu, q0, 2);
        q0 += __shfl_down_sync(0xffffffffu, q0, 1);
        s1 += __shfl_down_sync(0xffffffffu, s1, 2);
        s1 += __shfl_down_sync(0xffffffffu, s1, 1);
        q1 += __shfl_down_sync(0xffffffffu, q1, 2);
        q1 += __shfl_down_sync(0xffffffffu, q1, 1);
        if (tig == 0) {
            int lo = wm*32 + m*16 + g;
            atomicAdd(&sS[lo    ], s0);
            atomicAdd(&sQ[lo    ], q0);
            atomicAdd(&sS[lo + 8], s1);
            atomicAdd(&sQ[lo + 8], q1);
        }
    }
    __syncthreads();
    if (t < 64) {
        atomicAdd(&g_bnsum[ocblk*64 + t], sS[t]);
        atomicAdd(&g_bnsq [ocblk*64 + t], sQ[t]);
    }
}

// =================================================================
// BN finalize: per-oc scale/shift from accumulated sums (1 block, 256 thr)
// =================================================================
__global__ void k_bnfin(const float* __restrict__ gg, const float* __restrict__ bb)
{
    int oc = threadIdx.x;
    float mean = g_bnsum[oc] * (1.f / (NB*NSP));
    float var  = g_bnsq[oc] * (1.f / (NB*NSP)) - mean*mean;
    float inv  = rsqrtf(var + 1e-5f);
    float sc = inv * gg[oc];
    g_scale[oc] = sc;
    g_shift[oc] = bb[oc] - mean * sc;
}

// =================================================================
// gate logits with BN+relu applied inline from raw c2X
// =================================================================
__global__ void k_gate(const float* __restrict__ wd)
{
    int i = blockIdx.x, b = blockIdx.y, j = threadIdx.x;
    __shared__ float wsh[C2C*HH];
    __shared__ float scs[C2C], shs[C2C];
    for (int s = j; s < C2C*HH; s += NN) {
        int c = s >> 3, h = s & 7;
        wsh[s] = wd[h*C2C + c];
    }
    for (int s = j; s < C2C; s += NN) { scs[s] = g_scale[s]; shs[s] = g_shift[s]; }
    __syncthreads();
    float acc[HH] = {};
    const float* base = g_c2X + (size_t)(b*C2C)*NSP + i*NN + j;
    #pragma unroll 4
    for (int c = 0; c < C2C; ++c) {
        float v = fmaxf(fmaf(base[(size_t)c*NSP], scs[c], shs[c]), 0.f);
        #pragma unroll
        for (int h = 0; h < HH; ++h) acc[h] += v * wsh[c*8 + h];
    }
    #pragma unroll
    for (int h = 0; h < HH; ++h)
        g_G[((b*HH + h)*NN + i)*NN + j] = acc[h];
}

// =================================================================
// Generic 384x128x128 GEMM with relu epilogue.
// =================================================================
__global__ void k_gemm64(int asel, int addupd,
                         const float* __restrict__ W,
                         const float* __restrict__ bias,
                         int outsel, float* dptr)
{
    __shared__ float As[32*68];
    __shared__ float Ws[32*68];
    int t = threadIdx.x;
    int tx = t & 15, ty = t >> 4;
    int rowbase = blockIdx.y * 64, colbase = blockIdx.x * 64;

    const float* A = asel ? g_xB : g_xA;
    float* outp;
    if      (outsel == 3) { outp = g_xA; }
    else if (outsel == 4) { outp = g_xB; }
    else                  { outp = dptr; }

    float acc[4][4] = {};
    for (int kk = 0; kk < 128; kk += 32) {
        #pragma unroll
        for (int r = 0; r < 8; ++r) {
            int s = r*256 + t;
            int row = s >> 5, e = s & 31;
            float v = A[(rowbase + row)*DIMD + kk + e];
            if (addupd) v += g_upd[(rowbase + row)*DIMD + kk + e];
            As[e*68 + row] = v;
            Ws[e*68 + row] = W[(colbase + row)*DIMD + kk + e];
        }
        __syncthreads();
        #pragma unroll
        for (int e = 0; e < 32; ++e) {
            float a0 = As[e*68 + ty*4 + 0], a1 = As[e*68 + ty*4 + 1];
            float a2 = As[e*68 + ty*4 + 2], a3 = As[e*68 + ty*4 + 3];
            float w0 = Ws[e*68 + tx*4 + 0], w1 = Ws[e*68 + tx*4 + 1];
            float w2 = Ws[e*68 + tx*4 + 2], w3 = Ws[e*68 + tx*4 + 3];
            acc[0][0] += a0*w0; acc[0][1] += a0*w1; acc[0][2] += a0*w2; acc[0][3] += a0*w3;
            acc[1][0] += a1*w0; acc[1][1] += a1*w1; acc[1][2] += a1*w2; acc[1][3] += a1*w3;
            acc[2][0] += a2*w0; acc[2][1] += a2*w1; acc[2][2] += a2*w2; acc[2][3] += a2*w3;
            acc[3][0] += a3*w0; acc[3][1] += a3*w1; acc[3][2] += a3*w2; acc[3][3] += a3*w3;
        }
        __syncthreads();
    }

    #pragma unroll
    for (int v = 0; v < 4; ++v) {
        int row = rowbase + ty*4 + v;
        #pragma unroll
        for (int u = 0; u < 4; ++u) {
            int col = colbase + tx*4 + u;
            float r = fmaxf(acc[v][u] + bias[col], 0.f);
            outp[row*DIMD + col] = r;
        }
    }
}

// =================================================================
// fused q/k/v GEMM: one launch, 3 weight sets; grid (6, 6).
// =================================================================
__global__ void k_gemm_qkv(int asel,
                           const float* __restrict__ Wq, const float* __restrict__ bq,
                           const float* __restrict__ Wk, const float* __restrict__ bk,
                           const float* __restrict__ Wv, const float* __restrict__ bv)
{
    __shared__ float As[32*68];
    __shared__ float Ws[32*68];
    int t = threadIdx.x;
    int tx = t & 15, ty = t >> 4;
    int sel = blockIdx.x >> 1;
    int rowbase = blockIdx.y * 64, colbase = (blockIdx.x & 1) * 64;

    const float* A = asel ? g_xB : g_xA;
    const float* W    = (sel == 0) ? Wq : (sel == 1) ? Wk : Wv;
    const float* bias = (sel == 0) ? bq : (sel == 1) ? bk : bv;
    float* outp       = (sel == 0) ? g_q : (sel == 1) ? g_k : g_v;

    float acc[4][4] = {};
    for (int kk = 0; kk < 128; kk += 32) {
        #pragma unroll
        for (int r = 0; r < 8; ++r) {
            int s = r*256 + t;
            int row = s >> 5, e = s & 31;
            As[e*68 + row] = A[(rowbase + row)*DIMD + kk + e];
            Ws[e*68 + row] = W[(colbase + row)*DIMD + kk + e];
        }
        __syncthreads();
        #pragma unroll
        for (int e = 0; e < 32; ++e) {
            float a0 = As[e*68 + ty*4 + 0], a1 = As[e*68 + ty*4 + 1];
            float a2 = As[e*68 + ty*4 + 2], a3 = As[e*68 + ty*4 + 3];
            float w0 = Ws[e*68 + tx*4 + 0], w1 = Ws[e*68 + tx*4 + 1];
            float w2 = Ws[e*68 + tx*4 + 2], w3 = Ws[e*68 + tx*4 + 3];
            acc[0][0] += a0*w0; acc[0][1] += a0*w1; acc[0][2] += a0*w2; acc[0][3] += a0*w3;
            acc[1][0] += a1*w0; acc[1][1] += a1*w1; acc[1][2] += a1*w2; acc[1][3] += a1*w3;
            acc[2][0] += a2*w0; acc[2][1] += a2*w1; acc[2][2] += a2*w2; acc[2][3] += a2*w3;
            acc[3][0] += a3*w0; acc[3][1] += a3*w1; acc[3][2] += a3*w2; acc[3][3] += a3*w3;
        }
        __syncthreads();
    }

    #pragma unroll
    for (int v = 0; v < 4; ++v) {
        int row = rowbase + ty*4 + v;
        #pragma unroll
        for (int u = 0; u < 4; ++u) {
            int col = colbase + tx*4 + u;
            float r = fmaxf(acc[v][u] + bias[col], 0.f);
            int b = row / NN, n = row % NN, h = col >> 4, dh = col & 15;
            outp[((b*HH + h)*NN + n)*DHH + dh] = r;
        }
    }
}

// =================================================================
// Attention + gate
// =================================================================
__global__ void k_attn(const float* __restrict__ mask,
                       const float* __restrict__ wdb)
{
    int i = blockIdx.x, h = blockIdx.y, b = blockIdx.z;
    int t = threadIdx.x;
    int bh = b*HH + h;

    __shared__ float qi[DHH];
    __shared__ float att[NN];
    __shared__ float redm[8];
    __shared__ float reds[8];
    __shared__ float part[16][17];

    if (t < DHH) qi[t] = g_q[(bh*NN + i)*DHH + t];
    __syncthreads();

    float aval = 0.f;
    if (t < NN) {
        const float* kp = g_k + (bh*NN + t)*DHH;
        float s = 0.f;
        #pragma unroll
        for (int d = 0; d < DHH; ++d) s += qi[d] * kp[d];
        aval = s * 0.25f;
    }
    float mval = (t < NN) ? aval : -3e38f;
    #pragma unroll
    for (int o = 16; o; o >>= 1) mval = fmaxf(mval, __shfl_xor_sync(0xffffffffu, mval, o));
    if (!(t & 31)) redm[t >> 5] = mval;
    __syncthreads();
    float mx = redm[0];
    #pragma unroll
    for (int ww = 1; ww < 8; ++ww) mx = fmaxf(mx, redm[ww]);

    float e = (t < NN) ? expf(aval - mx) * mask[b*NN + t] : 0.f;
    float sv = e;
    #pragma unroll
    for (int o = 16; o; o >>= 1) sv += __shfl_xor_sync(0xffffffffu, sv, o);
    if (!(t & 31)) reds[t >> 5] = sv;
    __syncthreads();
    float den = 1e-6f;
    #pragma unroll
    for (int ww = 0; ww < 8; ++ww) den += reds[ww];

    if (t < NN) {
        float gl = g_G[(bh*NN + i)*NN + t] + g_G[(bh*NN + t)*NN + i] + wdb[h];
        float gate = 1.f / (1.f + expf(-gl));
        att[t] = (e / den) * gate;
    }
    __syncthreads();

    int d = t & 15, grp = t >> 4;
    float p = 0.f;
    #pragma unroll
    for (int jj = 0; jj < 12; ++jj) {
        int j = grp*12 + jj;
        p += att[j] * g_v[(bh*NN + j)*DHH + d];
    }
    part[grp][d] = p;
    __syncthreads();
    if (t < DHH) {
        float s = 0.f;
        #pragma unroll
        for (int gg = 0; gg < 16; ++gg) s += part[gg][t];
        g_upd[(b*NN + i)*DIMD + h*DHH + t] = s;
    }
}

// =================================================================
// host
// =================================================================
extern "C" void kernel_launch(void* const* d_in, const int* in_sizes, int n_in,
                              void* d_out, int out_size)
{
    const float* seq     = (const float*)d_in[0];
    const float* mask    = (const float*)d_in[1];
    const float* conv1_w = (const float*)d_in[2];
    const float* conv2_w = (const float*)d_in[3];
    const float* ln_g    = (const float*)d_in[4];
    const float* ln_b    = (const float*)d_in[5];
    const float* c1d_w   = (const float*)d_in[6];
    const float* bn1_g   = (const float*)d_in[7];
    const float* bn1_b   = (const float*)d_in[8];
    const float* c2d_w   = (const float*)d_in[9];
    const float* bn2_g   = (const float*)d_in[10];
    const float* bn2_b   = (const float*)d_in[11];
    const float* wq_w    = (const float*)d_in[12];
    const float* wq_b    = (const float*)d_in[13];
    const float* wk_w    = (const float*)d_in[14];
    const float* wk_b    = (const float*)d_in[15];
    const float* wv_w    = (const float*)d_in[16];
    const float* wv_b    = (const float*)d_in[17];
    const float* wd_w    = (const float*)d_in[18];
    const float* wd_b    = (const float*)d_in[19];
    const float* wl_w    = (const float*)d_in[20];
    const float* wl_b    = (const float*)d_in[21];
    const float* fc_w    = (const float*)d_in[22];
    const float* fc_b    = (const float*)d_in[23];
    float* out = (float*)d_out;

    static int smem_set = 0;
    if (!smem_set) {
        cudaFuncSetAttribute(k_conv2d_mma, cudaFuncAttributeMaxDynamicSharedMemorySize, CONV_SMEM);
        smem_set = 1;
    }

    k_stem<<<dim3(NN, NB), 128>>>(seq, conv1_w, conv2_w);
    k_pair0<<<C2TOT/256, 256>>>();

    int xs = 0;
    for (int l = 0; l < 3; ++l) {
        int rd   = l & 1;        // which buffer holds incoming c
        int cnew = rd ^ 1;       // buffer that will hold new c

        k_conv1bn<<<DIMD, 384>>>(rd, c1d_w + l*DIMD*DIMD*3, bn1_g + l*DIMD, bn1_b + l*DIMD);
        k_ln<<<dim3(NN, NB), DIMD>>>(xs, cnew, ln_g + l*DIMD, ln_b + l*DIMD);
        k_splitw<<<1152, 256>>>(c2d_w + l*C2C*C2C*9);
        k_prep<<<BPTOT/256, 256>>>(cnew, l > 0 ? 1 : 0);
        k_conv2d_mma<<<dim3(4, NN, NB), 256, CONV_SMEM>>>();
        k_bnfin<<<1, 256>>>(bn2_g + l*C2C, bn2_b + l*C2C);
        k_gate<<<dim3(NN, NB), NN>>>(wd_w + l*HH*C2C);
        k_gemm_qkv<<<dim3(6, 6), 256>>>(xs, wq_w + l*DIMD*DIMD, wq_b + l*DIMD,
                                            wk_w + l*DIMD*DIMD, wk_b + l*DIMD,
                                            wv_w + l*DIMD*DIMD, wv_b + l*DIMD);
        k_attn<<<dim3(NN, HH, NB), 256>>>(mask, wd_b + l*HH);
        k_gemm64<<<dim3(2, 6), 256>>>(xs, 1, wl_w + l*DIMD*DIMD, wl_b + l*DIMD, xs ? 3 : 4, nullptr);
        xs ^= 1;
    }
    k_gemm64<<<dim3(2, 6), 256>>>(xs, 0, fc_w, fc_b, 5, out);
}

// round 15
// speedup vs baseline: 4.6811x; 1.4563x over previous
#include <cuda_runtime.h>
#include <cuda_fp16.h>
#include <cstdint>

// ---------------- problem constants ----------------
#define NB   2
#define NN   192
#define IND  20
#define DIMD 128
#define HH   8
#define DHH  16
#define C2C  256
#define NSP  (NN*NN)            // 36864
#define C2TOT (NB*C2C*NSP)      // 18874368

// ---------------- scratch (device globals; no allocation allowed) ----------------
__device__ float g_xA[NB*NN*DIMD];
__device__ float g_xB[NB*NN*DIMD];
__device__ float g_cA[NB*DIMD*NN];
__device__ float g_cB[NB*DIMD*NN];
__device__ float g_q[NB*HH*NN*DHH];
__device__ float g_k[NB*HH*NN*DHH];
__device__ float g_v[NB*HH*NN*DHH];
__device__ float g_upd[NB*NN*DIMD];
__device__ float g_G[NB*HH*NSP];
__device__ float g_scale[C2C];
__device__ float g_shift[C2C];
__device__ float g_bnsum[C2C];
__device__ float g_bnsq[C2C];
__device__ float g_c2A[C2TOT];     // layer-0 initial pair state only
__device__ float g_c2X[C2TOT];     // raw conv2d output (pre-BN)
// fp16 conv weights packed (ic even | ic odd<<16): [ocblk4][icc16][tap9][icpair8][oc64]
__device__ unsigned g_Wq[C2C*C2C*9/2];
// fp16 conv input packed by ic-pair: [b2][icpair128][row192][j192]
#define BPTOT (NB*128*NN*NN)    // 9437184
__device__ unsigned g_Bh[BPTOT];

// =================================================================
// Stem: x = conv1d(seq^T, conv1_w)^T ; c = conv1d(seq^T, conv2_w)
// =================================================================
__global__ void k_stem(const float* __restrict__ seq,
                       const float* __restrict__ w1,
                       const float* __restrict__ w2)
{
    int n = blockIdx.x, b = blockIdx.y, d = threadIdx.x;
    __shared__ float s3[3][IND];
    if (d < 3*IND) {
        int r = d / IND, ic = d % IND;
        int nn = n - 1 + r;
        s3[r][ic] = (nn >= 0 && nn < NN) ? seq[(b*NN + nn)*IND + ic] : 0.f;
    }
    __syncthreads();
    float ax = 0.f, ac = 0.f;
    #pragma unroll
    for (int ic = 0; ic < IND; ++ic) {
        #pragma unroll
        for (int r = 0; r < 3; ++r) {
            float v = s3[r][ic];
            ax += v * w1[(d*IND + ic)*3 + r];
            ac += v * w2[(d*IND + ic)*3 + r];
        }
    }
    g_xA[(b*NN + n)*DIMD + d] = ax;
    g_cA[(b*DIMD + d)*NN + n] = ac;
}

// =================================================================
// init pair state:  c2A = seq2pair(cA)
// =================================================================
__global__ void k_pair0()
{
    int idx = blockIdx.x * blockDim.x + threadIdx.x;
    int j  = idx % NN;
    int r1 = idx / NN;
    int i  = r1 % NN;
    int r2 = r1 / NN;
    int ch = r2 % C2C;
    int b  = r2 / C2C;
    float pv = (ch < DIMD) ? g_cA[(b*DIMD + ch)*NN + i]
                           : g_cA[(b*DIMD + (ch - DIMD))*NN + j];
    g_c2A[idx] = pv;
}

// =================================================================
// c = relu(bn1(conv1d(c, c1d_w[l])))  — chunked smem staging.
// =================================================================
__global__ void __launch_bounds__(384)
k_conv1bn(int rd, const float* __restrict__ w,
          const float* __restrict__ gg, const float* __restrict__ bb)
{
    int d = blockIdx.x;
    int t = threadIdx.x;
    int b = t / NN, n = t % NN;
    const float* c  = rd ? g_cB : g_cA;
    float*       co = rd ? g_cA : g_cB;

    __shared__ float sc[16][2][194];
    __shared__ float wsh[DIMD*3];
    __shared__ float red[2][12];

    wsh[t] = w[d*DIMD*3 + t];
    if (t < 32) { sc[t >> 1][t & 1][0] = 0.f; sc[t >> 1][t & 1][193] = 0.f; }
    __syncthreads();

    float acc = 0.f;
    for (int ec = 0; ec < DIMD; ec += 16) {
        #pragma unroll
        for (int q = 0; q < 16; ++q) {
            int s = q*384 + t;
            int e1 = s / 384;
            int rem = s - e1*384;
            int bb2 = rem / NN, n2 = rem - bb2*NN;
            sc[e1][bb2][n2 + 1] = c[((bb2*DIMD) + ec + e1)*NN + n2];
        }
        __syncthreads();
        #pragma unroll
        for (int e1 = 0; e1 < 16; ++e1) {
            int e = ec + e1;
            acc += sc[e1][b][n]     * wsh[e*3 + 0]
                 + sc[e1][b][n + 1] * wsh[e*3 + 1]
                 + sc[e1][b][n + 2] * wsh[e*3 + 2];
        }
        __syncthreads();
    }

    float s = acc, ss = acc * acc;
    #pragma unroll
    for (int o = 16; o; o >>= 1) {
        s  += __shfl_down_sync(0xffffffffu, s,  o);
        ss += __shfl_down_sync(0xffffffffu, ss, o);
    }
    if (!(t & 31)) { red[0][t >> 5] = s; red[1][t >> 5] = ss; }
    __syncthreads();
    float ts = 0.f, tss = 0.f;
    #pragma unroll
    for (int ww = 0; ww < 12; ++ww) { ts += red[0][ww]; tss += red[1][ww]; }
    float mean = ts * (1.f/384.f);
    float var  = tss * (1.f/384.f) - mean*mean;
    float inv  = rsqrtf(var + 1e-5f);

    float outv = fmaxf((acc - mean) * inv * gg[d] + bb[d], 0.f);
    co[(b*DIMD + d)*NN + n] = outv;
}

// =================================================================
// x = LN(x + c^T)
// =================================================================
__global__ void k_ln(int xs, int cs,
                     const float* __restrict__ gg, const float* __restrict__ bb)
{
    int n = blockIdx.x, b = blockIdx.y, d = threadIdx.x;
    float*       x = xs ? g_xB : g_xA;
    const float* c = cs ? g_cB : g_cA;

    float v = x[(b*NN + n)*DIMD + d] + c[(b*DIMD + d)*NN + n];

    __shared__ float red[2][4];
    float s = v, ss = v*v;
    #pragma unroll
    for (int o = 16; o; o >>= 1) {
        s  += __shfl_down_sync(0xffffffffu, s,  o);
        ss += __shfl_down_sync(0xffffffffu, ss, o);
    }
    if (!(d & 31)) { red[0][d >> 5] = s; red[1][d >> 5] = ss; }
    __syncthreads();
    float m   = (red[0][0]+red[0][1]+red[0][2]+red[0][3]) * (1.f/128.f);
    float var = (red[1][0]+red[1][1]+red[1][2]+red[1][3]) * (1.f/128.f) - m*m;
    float inv = rsqrtf(var + 1e-5f);
    x[(b*NN + n)*DIMD + d] = (v - m) * inv * gg[d] + bb[d];
}

// =================================================================
// conv2d weights -> single fp16, packed pairs along ic; also zeros BN accum.
// grid = 1152 x 256 (294912 u32)
// =================================================================
__global__ void k_splitw(const float* __restrict__ w)   // w: [256][256][9]
{
    int o = blockIdx.x * 256 + threadIdx.x;
    int oc    = o & 63;
    int p     = (o >> 6) & 7;
    int tap   = (o >> 9) % 9;
    int icc   = (o / 4608) & 15;
    int ocblk = o / 73728;
    int ocg = ocblk*64 + oc;
    int ic0 = icc*16 + 2*p;
    __half h0 = __float2half(w[(ocg*C2C + ic0    )*9 + tap]);
    __half h1 = __float2half(w[(ocg*C2C + ic0 + 1)*9 + tap]);
    g_Wq[o] = ((unsigned)__half_as_ushort(h1) << 16) | __half_as_ushort(h0);
    if (o < C2C) { g_bnsum[o] = 0.f; g_bnsq[o] = 0.f; }
}

// =================================================================
// prep conv2d input: v = state + seq2pair(c_cur)
// state = c2A (mode 0) or relu(bn_prev(c2X)) inline (mode 1).
// single fp16, packed (ic even | ic odd<<16) at [b][icpair][row][j].
// grid 36864 x 256
// =================================================================
__global__ void k_prep(int csel, int mode)
{
    int idx = blockIdx.x * 256 + threadIdx.x;      // 0..BPTOT-1
    int j   = idx % NN;
    int r1  = idx / NN;
    int row = r1 % NN;
    int r2  = r1 / NN;
    int icp = r2 % 128;
    int b   = r2 / 128;
    const float* cc = csel ? g_cB : g_cA;

    int ic0 = icp*2, ic1 = ic0 + 1;
    size_t s0 = ((size_t)(b*C2C + ic0)*NN + row)*NN + j;
    size_t s1 = ((size_t)(b*C2C + ic1)*NN + row)*NN + j;
    float st0, st1;
    if (mode) {
        st0 = fmaxf(fmaf(g_c2X[s0], g_scale[ic0], g_shift[ic0]), 0.f);
        st1 = fmaxf(fmaf(g_c2X[s1], g_scale[ic1], g_shift[ic1]), 0.f);
    } else {
        st0 = g_c2A[s0];
        st1 = g_c2A[s1];
    }
    float x0 = st0 + ((ic0 < DIMD) ? cc[(b*DIMD + ic0)*NN + row]
                                   : cc[(b*DIMD + ic0 - DIMD)*NN + j]);
    float x1 = st1 + ((ic1 < DIMD) ? cc[(b*DIMD + ic1)*NN + row]
                                   : cc[(b*DIMD + ic1 - DIMD)*NN + j]);

    __half h0 = __float2half(x0);
    __half h1 = __float2half(x1);
    g_Bh[idx] = ((unsigned)__half_as_ushort(h1) << 16) | __half_as_ushort(h0);
}

// =================================================================
// conv2d 3x3 C2->C2 on tensor cores (fp16 1-term, mma.m16n8k16).
// Input in g_Bh (fp16), weights in g_Wq (fp16).  Raw fp32 out -> g_c2X.
// Epilogue accumulates per-oc sum/sumsq into g_bnsum/g_bnsq.
// CTA: 64 oc x output row i x batch.  8 warps: 32 oc x 48 j each.
// Smem (u32): Aq [tap9][icpair8][oc stride 72]   (5184)
//             Bq [r3*icpair8][col stride 200]    (4800), data at col 4..195
// =================================================================
#define MMA_F16(c0,c1,c2,c3, A0,A1,A2,A3, B0,B1)                          \
  asm volatile("mma.sync.aligned.m16n8k16.row.col.f32.f16.f16.f32 "       \
    "{%0,%1,%2,%3},{%4,%5,%6,%7},{%8,%9},{%0,%1,%2,%3};"                  \
    : "+f"(c0),"+f"(c1),"+f"(c2),"+f"(c3)                                 \
    : "r"(A0),"r"(A1),"r"(A2),"r"(A3),"r"(B0),"r"(B1))

#define ASZ 5184
#define BSZ 4800
#define CONV_SMEM ((ASZ + BSZ)*4)   // 39936 B

__global__ void __launch_bounds__(256, 2)
k_conv2d_mma()
{
    extern __shared__ unsigned smu[];
    unsigned* Aq = smu;
    unsigned* Bq = smu + ASZ;
    __shared__ float sS[64], sQ[64];

    int ocblk = blockIdx.x;       // 0..3
    int i     = blockIdx.y;       // 0..191
    int b     = blockIdx.z;       // 0..1
    int t = threadIdx.x;
    int w = t >> 5, lane = t & 31;
    int g = lane >> 2, tig = lane & 3;
    int wm = w & 1, wn = w >> 1;

    // zero B halo columns + stats accumulators (written once)
    if (t < 192) {
        int rr = t / 8, cq = t & 7;
        int col = (cq < 4) ? cq : (192 + cq);
        Bq[rr*200 + col] = 0u;
    }
    if (t < 64) { sS[t] = 0.f; sQ[t] = 0.f; }

    float acc[2][6][4];
    #pragma unroll
    for (int m = 0; m < 2; ++m)
        #pragma unroll
        for (int u = 0; u < 6; ++u)
            #pragma unroll
            for (int q = 0; q < 4; ++q) acc[m][u][q] = 0.f;

    const unsigned* wsrc = g_Wq + ocblk*73728;

    for (int icc = 0; icc < 16; ++icc) {
        // ---- stage weights (1152 uint4) + input (1152 uint4) combined ----
        #pragma unroll
        for (int q = 0; q < 9; ++q) {
            int sidx = q*256 + t;
            if (sidx < 1152) {
                int s4 = sidx * 4;
                int tap = s4 >> 9, p = (s4 >> 6) & 7, oc = s4 & 63;
                ((uint4*)Aq)[((tap*8 + p)*72 + oc) >> 2] =
                    ((const uint4*)wsrc)[icc*1152 + sidx];
            } else {
                int s2 = sidx - 1152;
                int seg = s2 / 48, v4 = s2 - seg*48;   // seg = r*8+icp
                int r = seg >> 3, icp = seg & 7;
                int row = i - 1 + r;
                uint4 val = make_uint4(0u,0u,0u,0u);
                if (row >= 0 && row < NN)
                    val = ((const uint4*)g_Bh)
                            [(size_t)((b*128 + icc*8 + icp)*NN + row)*48 + v4];
                ((uint4*)Bq)[(seg*200 + 4 + v4*4) >> 2] = val;
            }
        }
        __syncthreads();

        #pragma unroll
        for (int r = 0; r < 3; ++r) {
            #pragma unroll
            for (int dj = 0; dj < 3; ++dj) {
                int tap = r*3 + dj;
                unsigned aq[2][4];
                #pragma unroll
                for (int m = 0; m < 2; ++m) {
                    int mb = wm*32 + m*16 + g;
                    aq[m][0] = Aq[(tap*8 + tig    )*72 + mb    ];
                    aq[m][1] = Aq[(tap*8 + tig    )*72 + mb + 8];
                    aq[m][2] = Aq[(tap*8 + tig + 4)*72 + mb    ];
                    aq[m][3] = Aq[(tap*8 + tig + 4)*72 + mb + 8];
                }
                #pragma unroll
                for (int u = 0; u < 6; ++u) {
                    int col = wn*48 + u*8 + g + dj + 3;
                    unsigned b0 = Bq[(r*8 + tig    )*200 + col];
                    unsigned b1 = Bq[(r*8 + tig + 4)*200 + col];
                    #pragma unroll
                    for (int m = 0; m < 2; ++m) {
                        float* c = acc[m][u];
                        MMA_F16(c[0],c[1],c[2],c[3],
                                aq[m][0],aq[m][1],aq[m][2],aq[m][3], b0,b1);
                    }
                }
            }
        }
        __syncthreads();
    }

    // ---- epilogue: write raw conv output + per-oc stats partials ----
    #pragma unroll
    for (int m = 0; m < 2; ++m) {
        int oc0 = ocblk*64 + wm*32 + m*16 + g;
        float s0 = 0.f, q0 = 0.f, s1 = 0.f, q1 = 0.f;
        #pragma unroll
        for (int u = 0; u < 6; ++u) {
            int j = wn*48 + u*8 + 2*tig;
            float a0 = acc[m][u][0], a1 = acc[m][u][1];
            float a2 = acc[m][u][2], a3 = acc[m][u][3];
            s0 += a0 + a1;  q0 += a0*a0 + a1*a1;
            s1 += a2 + a3;  q1 += a2*a2 + a3*a3;
            *(float2*)&g_c2X[((size_t)(b*C2C + oc0    )*NN + i)*NN + j] = make_float2(a0, a1);
            *(float2*)&g_c2X[((size_t)(b*C2C + oc0 + 8)*NN + i)*NN + j] = make_float2(a2, a3);
        }
        s0 += __shfl_down_sync(0xffffffffu, s0, 2);
        s0 += __shfl_down_sync(0xffffffffu, s0, 1);
        q0 += __shfl_down_sync(0xffffffffu, q0, 2);
        q0 += __shfl_down_sync(0xffffffffu, q0, 1);
        s1 += __shfl_down_sync(0xffffffffu, s1, 2);
        s1 += __shfl_down_sync(0xffffffffu, s1, 1);
        q1 += __shfl_down_sync(0xffffffffu, q1, 2);
        q1 += __shfl_down_sync(0xffffffffu, q1, 1);
        if (tig == 0) {
            int lo = wm*32 + m*16 + g;
            atomicAdd(&sS[lo    ], s0);
            atomicAdd(&sQ[lo    ], q0);
            atomicAdd(&sS[lo + 8], s1);
            atomicAdd(&sQ[lo + 8], q1);
        }
    }
    __syncthreads();
    if (t < 64) {
        atomicAdd(&g_bnsum[ocblk*64 + t], sS[t]);
        atomicAdd(&g_bnsq [ocblk*64 + t], sQ[t]);
    }
}

// =================================================================
// BN finalize: per-oc scale/shift from accumulated sums (1 block, 256 thr)
// =================================================================
__global__ void k_bnfin(const float* __restrict__ gg, const float* __restrict__ bb)
{
    int oc = threadIdx.x;
    float mean = g_bnsum[oc] * (1.f / (NB*NSP));
    float var  = g_bnsq[oc] * (1.f / (NB*NSP)) - mean*mean;
    float inv  = rsqrtf(var + 1e-5f);
    float sc = inv * gg[oc];
    g_scale[oc] = sc;
    g_shift[oc] = bb[oc] - mean * sc;
}

// =================================================================
// gate logits with BN+relu applied inline from raw c2X
// =================================================================
__global__ void k_gate(const float* __restrict__ wd)
{
    int i = blockIdx.x, b = blockIdx.y, j = threadIdx.x;
    __shared__ float wsh[C2C*HH];
    __shared__ float scs[C2C], shs[C2C];
    for (int s = j; s < C2C*HH; s += NN) {
        int c = s >> 3, h = s & 7;
        wsh[s] = wd[h*C2C + c];
    }
    for (int s = j; s < C2C; s += NN) { scs[s] = g_scale[s]; shs[s] = g_shift[s]; }
    __syncthreads();
    float acc[HH] = {};
    const float* base = g_c2X + (size_t)(b*C2C)*NSP + i*NN + j;
    #pragma unroll 4
    for (int c = 0; c < C2C; ++c) {
        float v = fmaxf(fmaf(base[(size_t)c*NSP], scs[c], shs[c]), 0.f);
        #pragma unroll
        for (int h = 0; h < HH; ++h) acc[h] += v * wsh[c*8 + h];
    }
    #pragma unroll
    for (int h = 0; h < HH; ++h)
        g_G[((b*HH + h)*NN + i)*NN + j] = acc[h];
}

// =================================================================
// Generic 384x128x128 GEMM with relu epilogue.
// =================================================================
__global__ void k_gemm64(int asel, int addupd,
                         const float* __restrict__ W,
                         const float* __restrict__ bias,
                         int outsel, float* dptr)
{
    __shared__ float As[32*68];
    __shared__ float Ws[32*68];
    int t = threadIdx.x;
    int tx = t & 15, ty = t >> 4;
    int rowbase = blockIdx.y * 64, colbase = blockIdx.x * 64;

    const float* A = asel ? g_xB : g_xA;
    float* outp;
    if      (outsel == 3) { outp = g_xA; }
    else if (outsel == 4) { outp = g_xB; }
    else                  { outp = dptr; }

    float acc[4][4] = {};
    for (int kk = 0; kk < 128; kk += 32) {
        #pragma unroll
        for (int r = 0; r < 8; ++r) {
            int s = r*256 + t;
            int row = s >> 5, e = s & 31;
            float v = A[(rowbase + row)*DIMD + kk + e];
            if (addupd) v += g_upd[(rowbase + row)*DIMD + kk + e];
            As[e*68 + row] = v;
            Ws[e*68 + row] = W[(colbase + row)*DIMD + kk + e];
        }
        __syncthreads();
        #pragma unroll
        for (int e = 0; e < 32; ++e) {
            float a0 = As[e*68 + ty*4 + 0], a1 = As[e*68 + ty*4 + 1];
            float a2 = As[e*68 + ty*4 + 2], a3 = As[e*68 + ty*4 + 3];
            float w0 = Ws[e*68 + tx*4 + 0], w1 = Ws[e*68 + tx*4 + 1];
            float w2 = Ws[e*68 + tx*4 + 2], w3 = Ws[e*68 + tx*4 + 3];
            acc[0][0] += a0*w0; acc[0][1] += a0*w1; acc[0][2] += a0*w2; acc[0][3] += a0*w3;
            acc[1][0] += a1*w0; acc[1][1] += a1*w1; acc[1][2] += a1*w2; acc[1][3] += a1*w3;
            acc[2][0] += a2*w0; acc[2][1] += a2*w1; acc[2][2] += a2*w2; acc[2][3] += a2*w3;
            acc[3][0] += a3*w0; acc[3][1] += a3*w1; acc[3][2] += a3*w2; acc[3][3] += a3*w3;
        }
        __syncthreads();
    }

    #pragma unroll
    for (int v = 0; v < 4; ++v) {
        int row = rowbase + ty*4 + v;
        #pragma unroll
        for (int u = 0; u < 4; ++u) {
            int col = colbase + tx*4 + u;
            float r = fmaxf(acc[v][u] + bias[col], 0.f);
            outp[row*DIMD + col] = r;
        }
    }
}

// =================================================================
// fused q/k/v GEMM: one launch, 3 weight sets; grid (6, 6).
// =================================================================
__global__ void k_gemm_qkv(int asel,
                           const float* __restrict__ Wq, const float* __restrict__ bq,
                           const float* __restrict__ Wk, const float* __restrict__ bk,
                           const float* __restrict__ Wv, const float* __restrict__ bv)
{
    __shared__ float As[32*68];
    __shared__ float Ws[32*68];
    int t = threadIdx.x;
    int tx = t & 15, ty = t >> 4;
    int sel = blockIdx.x >> 1;
    int rowbase = blockIdx.y * 64, colbase = (blockIdx.x & 1) * 64;

    const float* A = asel ? g_xB : g_xA;
    const float* W    = (sel == 0) ? Wq : (sel == 1) ? Wk : Wv;
    const float* bias = (sel == 0) ? bq : (sel == 1) ? bk : bv;
    float* outp       = (sel == 0) ? g_q : (sel == 1) ? g_k : g_v;

    float acc[4][4] = {};
    for (int kk = 0; kk < 128; kk += 32) {
        #pragma unroll
        for (int r = 0; r < 8; ++r) {
            int s = r*256 + t;
            int row = s >> 5, e = s & 31;
            As[e*68 + row] = A[(rowbase + row)*DIMD + kk + e];
            Ws[e*68 + row] = W[(colbase + row)*DIMD + kk + e];
        }
        __syncthreads();
        #pragma unroll
        for (int e = 0; e < 32; ++e) {
            float a0 = As[e*68 + ty*4 + 0], a1 = As[e*68 + ty*4 + 1];
            float a2 = As[e*68 + ty*4 + 2], a3 = As[e*68 + ty*4 + 3];
            float w0 = Ws[e*68 + tx*4 + 0], w1 = Ws[e*68 + tx*4 + 1];
            float w2 = Ws[e*68 + tx*4 + 2], w3 = Ws[e*68 + tx*4 + 3];
            acc[0][0] += a0*w0; acc[0][1] += a0*w1; acc[0][2] += a0*w2; acc[0][3] += a0*w3;
            acc[1][0] += a1*w0; acc[1][1] += a1*w1; acc[1][2] += a1*w2; acc[1][3] += a1*w3;
            acc[2][0] += a2*w0; acc[2][1] += a2*w1; acc[2][2] += a2*w2; acc[2][3] += a2*w3;
            acc[3][0] += a3*w0; acc[3][1] += a3*w1; acc[3][2] += a3*w2; acc[3][3] += a3*w3;
        }
        __syncthreads();
    }

    #pragma unroll
    for (int v = 0; v < 4; ++v) {
        int row = rowbase + ty*4 + v;
        #pragma unroll
        for (int u = 0; u < 4; ++u) {
            int col = colbase + tx*4 + u;
            float r = fmaxf(acc[v][u] + bias[col], 0.f);
            int b = row / NN, n = row % NN, h = col >> 4, dh = col & 15;
            outp[((b*HH + h)*NN + n)*DHH + dh] = r;
        }
    }
}

// =================================================================
// Attention + gate
// =================================================================
__global__ void k_attn(const float* __restrict__ mask,
                       const float* __restrict__ wdb)
{
    int i = blockIdx.x, h = blockIdx.y, b = blockIdx.z;
    int t = threadIdx.x;
    int bh = b*HH + h;

    __shared__ float qi[DHH];
    __shared__ float att[NN];
    __shared__ float redm[8];
    __shared__ float reds[8];
    __shared__ float part[16][17];

    if (t < DHH) qi[t] = g_q[(bh*NN + i)*DHH + t];
    __syncthreads();

    float aval = 0.f;
    if (t < NN) {
        const float* kp = g_k + (bh*NN + t)*DHH;
        float s = 0.f;
        #pragma unroll
        for (int d = 0; d < DHH; ++d) s += qi[d] * kp[d];
        aval = s * 0.25f;
    }
    float mval = (t < NN) ? aval : -3e38f;
    #pragma unroll
    for (int o = 16; o; o >>= 1) mval = fmaxf(mval, __shfl_xor_sync(0xffffffffu, mval, o));
    if (!(t & 31)) redm[t >> 5] = mval;
    __syncthreads();
    float mx = redm[0];
    #pragma unroll
    for (int ww = 1; ww < 8; ++ww) mx = fmaxf(mx, redm[ww]);

    float e = (t < NN) ? expf(aval - mx) * mask[b*NN + t] : 0.f;
    float sv = e;
    #pragma unroll
    for (int o = 16; o; o >>= 1) sv += __shfl_xor_sync(0xffffffffu, sv, o);
    if (!(t & 31)) reds[t >> 5] = sv;
    __syncthreads();
    float den = 1e-6f;
    #pragma unroll
    for (int ww = 0; ww < 8; ++ww) den += reds[ww];

    if (t < NN) {
        float gl = g_G[(bh*NN + i)*NN + t] + g_G[(bh*NN + t)*NN + i] + wdb[h];
        float gate = 1.f / (1.f + expf(-gl));
        att[t] = (e / den) * gate;
    }
    __syncthreads();

    int d = t & 15, grp = t >> 4;
    float p = 0.f;
    #pragma unroll
    for (int jj = 0; jj < 12; ++jj) {
        int j = grp*12 + jj;
        p += att[j] * g_v[(bh*NN + j)*DHH + d];
    }
    part[grp][d] = p;
    __syncthreads();
    if (t < DHH) {
        float s = 0.f;
        #pragma unroll
        for (int gg = 0; gg < 16; ++gg) s += part[gg][t];
        g_upd[(b*NN + i)*DIMD + h*DHH + t] = s;
    }
}

// =================================================================
// host
// =================================================================
extern "C" void kernel_launch(void* const* d_in, const int* in_sizes, int n_in,
                              void* d_out, int out_size)
{
    const float* seq     = (const float*)d_in[0];
    const float* mask    = (const float*)d_in[1];
    const float* conv1_w = (const float*)d_in[2];
    const float* conv2_w = (const float*)d_in[3];
    const float* ln_g    = (const float*)d_in[4];
    const float* ln_b    = (const float*)d_in[5];
    const float* c1d_w   = (const float*)d_in[6];
    const float* bn1_g   = (const float*)d_in[7];
    const float* bn1_b   = (const float*)d_in[8];
    const float* c2d_w   = (const float*)d_in[9];
    const float* bn2_g   = (const float*)d_in[10];
    const float* bn2_b   = (const float*)d_in[11];
    const float* wq_w    = (const float*)d_in[12];
    const float* wq_b    = (const float*)d_in[13];
    const float* wk_w    = (const float*)d_in[14];
    const float* wk_b    = (const float*)d_in[15];
    const float* wv_w    = (const float*)d_in[16];
    const float* wv_b    = (const float*)d_in[17];
    const float* wd_w    = (const float*)d_in[18];
    const float* wd_b    = (const float*)d_in[19];
    const float* wl_w    = (const float*)d_in[20];
    const float* wl_b    = (const float*)d_in[21];
    const float* fc_w    = (const float*)d_in[22];
    const float* fc_b    = (const float*)d_in[23];
    float* out = (float*)d_out;

    static int smem_set = 0;
    if (!smem_set) {
        cudaFuncSetAttribute(k_conv2d_mma, cudaFuncAttributeMaxDynamicSharedMemorySize, CONV_SMEM);
        smem_set = 1;
    }

    k_stem<<<dim3(NN, NB), 128>>>(seq, conv1_w, conv2_w);
    k_pair0<<<C2TOT/256, 256>>>();

    int xs = 0;
    for (int l = 0; l < 3; ++l) {
        int rd   = l & 1;        // which buffer holds incoming c
        int cnew = rd ^ 1;       // buffer that will hold new c

        k_conv1bn<<<DIMD, 384>>>(rd, c1d_w + l*DIMD*DIMD*3, bn1_g + l*DIMD, bn1_b + l*DIMD);
        k_ln<<<dim3(NN, NB), DIMD>>>(xs, cnew, ln_g + l*DIMD, ln_b + l*DIMD);
        k_splitw<<<1152, 256>>>(c2d_w + l*C2C*C2C*9);
        k_prep<<<BPTOT/256, 256>>>(cnew, l > 0 ? 1 : 0);
        k_conv2d_mma<<<dim3(4, NN, NB), 256, CONV_SMEM>>>();
        k_bnfin<<<1, 256>>>(bn2_g + l*C2C, bn2_b + l*C2C);
        k_gate<<<dim3(NN, NB), NN>>>(wd_w + l*HH*C2C);
        k_gemm_qkv<<<dim3(6, 6), 256>>>(xs, wq_w + l*DIMD*DIMD, wq_b + l*DIMD,
                                            wk_w + l*DIMD*DIMD, wk_b + l*DIMD,
                                            wv_w + l*DIMD*DIMD, wv_b + l*DIMD);
        k_attn<<<dim3(NN, HH, NB), 256>>>(mask, wd_b + l*HH);
        k_gemm64<<<dim3(2, 6), 256>>>(xs, 1, wl_w + l*DIMD*DIMD, wl_b + l*DIMD, xs ? 3 : 4, nullptr);
        xs ^= 1;
    }
    k_gemm64<<<dim3(2, 6), 256>>>(xs, 0, fc_w, fc_b, 5, out);
}

// round 16
// speedup vs baseline: 4.8951x; 1.0457x over previous
#include <cuda_runtime.h>
#include <cuda_fp16.h>
#include <cstdint>

// ---------------- problem constants ----------------
#define NB   2
#define NN   192
#define IND  20
#define DIMD 128
#define HH   8
#define DHH  16
#define C2C  256
#define NSP  (NN*NN)            // 36864
#define C2TOT (NB*C2C*NSP)      // 18874368

// ---------------- scratch (device globals; no allocation allowed) ----------------
__device__ float g_xA[NB*NN*DIMD];
__device__ float g_xB[NB*NN*DIMD];
__device__ float g_cA[NB*DIMD*NN];
__device__ float g_cB[NB*DIMD*NN];
__device__ float g_q[NB*HH*NN*DHH];
__device__ float g_k[NB*HH*NN*DHH];
__device__ float g_v[NB*HH*NN*DHH];
__device__ float g_upd[NB*NN*DIMD];
__device__ float g_G[NB*HH*NSP];
__device__ float g_scale[C2C];
__device__ float g_shift[C2C];
__device__ float g_bnsum[C2C];
__device__ float g_bnsq[C2C];
__device__ float g_c2A[C2TOT];     // layer-0 initial pair state only (fp32)
__device__ __half g_c2H[C2TOT];    // raw conv2d output (pre-BN), fp16
// fp16 conv weights packed (ic even | ic odd<<16): [ocblk4][icc16][tap9][icpair8][oc64]
__device__ unsigned g_Wq[C2C*C2C*9/2];
// fp16 conv input packed by ic-pair: [b2][icpair128][row192][j192]
#define BPTOT (NB*128*NN*NN)    // 9437184
__device__ unsigned g_Bh[BPTOT];

// =================================================================
// Stem: x = conv1d(seq^T, conv1_w)^T ; c = conv1d(seq^T, conv2_w)
// =================================================================
__global__ void k_stem(const float* __restrict__ seq,
                       const float* __restrict__ w1,
                       const float* __restrict__ w2)
{
    int n = blockIdx.x, b = blockIdx.y, d = threadIdx.x;
    __shared__ float s3[3][IND];
    if (d < 3*IND) {
        int r = d / IND, ic = d % IND;
        int nn = n - 1 + r;
        s3[r][ic] = (nn >= 0 && nn < NN) ? seq[(b*NN + nn)*IND + ic] : 0.f;
    }
    __syncthreads();
    float ax = 0.f, ac = 0.f;
    #pragma unroll
    for (int ic = 0; ic < IND; ++ic) {
        #pragma unroll
        for (int r = 0; r < 3; ++r) {
            float v = s3[r][ic];
            ax += v * w1[(d*IND + ic)*3 + r];
            ac += v * w2[(d*IND + ic)*3 + r];
        }
    }
    g_xA[(b*NN + n)*DIMD + d] = ax;
    g_cA[(b*DIMD + d)*NN + n] = ac;
}

// =================================================================
// init pair state:  c2A = seq2pair(cA)   (c_stem lives in cA)
// =================================================================
__global__ void k_pair0()
{
    int idx = blockIdx.x * blockDim.x + threadIdx.x;
    int j  = idx % NN;
    int r1 = idx / NN;
    int i  = r1 % NN;
    int r2 = r1 / NN;
    int ch = r2 % C2C;
    int b  = r2 / C2C;
    float pv = (ch < DIMD) ? g_cA[(b*DIMD + ch)*NN + i]
                           : g_cA[(b*DIMD + (ch - DIMD))*NN + j];
    g_c2A[idx] = pv;
}

// =================================================================
// c = relu(bn1(conv1d(c, c1d_w[l])))  — chunked smem staging.
// rd: reads rd?cB:cA, writes the other.
// =================================================================
__global__ void __launch_bounds__(384)
k_conv1bn(int rd, const float* __restrict__ w,
          const float* __restrict__ gg, const float* __restrict__ bb)
{
    int d = blockIdx.x;
    int t = threadIdx.x;
    int b = t / NN, n = t % NN;
    const float* c  = rd ? g_cB : g_cA;
    float*       co = rd ? g_cA : g_cB;

    __shared__ float sc[16][2][194];
    __shared__ float wsh[DIMD*3];
    __shared__ float red[2][12];

    wsh[t] = w[d*DIMD*3 + t];
    if (t < 32) { sc[t >> 1][t & 1][0] = 0.f; sc[t >> 1][t & 1][193] = 0.f; }
    __syncthreads();

    float acc = 0.f;
    for (int ec = 0; ec < DIMD; ec += 16) {
        #pragma unroll
        for (int q = 0; q < 16; ++q) {
            int s = q*384 + t;
            int e1 = s / 384;
            int rem = s - e1*384;
            int bb2 = rem / NN, n2 = rem - bb2*NN;
            sc[e1][bb2][n2 + 1] = c[((bb2*DIMD) + ec + e1)*NN + n2];
        }
        __syncthreads();
        #pragma unroll
        for (int e1 = 0; e1 < 16; ++e1) {
            int e = ec + e1;
            acc += sc[e1][b][n]     * wsh[e*3 + 0]
                 + sc[e1][b][n + 1] * wsh[e*3 + 1]
                 + sc[e1][b][n + 2] * wsh[e*3 + 2];
        }
        __syncthreads();
    }

    float s = acc, ss = acc * acc;
    #pragma unroll
    for (int o = 16; o; o >>= 1) {
        s  += __shfl_down_sync(0xffffffffu, s,  o);
        ss += __shfl_down_sync(0xffffffffu, ss, o);
    }
    if (!(t & 31)) { red[0][t >> 5] = s; red[1][t >> 5] = ss; }
    __syncthreads();
    float ts = 0.f, tss = 0.f;
    #pragma unroll
    for (int ww = 0; ww < 12; ++ww) { ts += red[0][ww]; tss += red[1][ww]; }
    float mean = ts * (1.f/384.f);
    float var  = tss * (1.f/384.f) - mean*mean;
    float inv  = rsqrtf(var + 1e-5f);

    float outv = fmaxf((acc - mean) * inv * gg[d] + bb[d], 0.f);
    co[(b*DIMD + d)*NN + n] = outv;
}

// =================================================================
// x = LN(x + c^T)
// =================================================================
__global__ void k_ln(int xs, int cs,
                     const float* __restrict__ gg, const float* __restrict__ bb)
{
    int n = blockIdx.x, b = blockIdx.y, d = threadIdx.x;
    float*       x = xs ? g_xB : g_xA;
    const float* c = cs ? g_cB : g_cA;

    float v = x[(b*NN + n)*DIMD + d] + c[(b*DIMD + d)*NN + n];

    __shared__ float red[2][4];
    float s = v, ss = v*v;
    #pragma unroll
    for (int o = 16; o; o >>= 1) {
        s  += __shfl_down_sync(0xffffffffu, s,  o);
        ss += __shfl_down_sync(0xffffffffu, ss, o);
    }
    if (!(d & 31)) { red[0][d >> 5] = s; red[1][d >> 5] = ss; }
    __syncthreads();
    float m   = (red[0][0]+red[0][1]+red[0][2]+red[0][3]) * (1.f/128.f);
    float var = (red[1][0]+red[1][1]+red[1][2]+red[1][3]) * (1.f/128.f) - m*m;
    float inv = rsqrtf(var + 1e-5f);
    x[(b*NN + n)*DIMD + d] = (v - m) * inv * gg[d] + bb[d];
}

// =================================================================
// conv2d weights -> single fp16, packed pairs along ic; also zeros BN accum.
// grid = 1152 x 256 (294912 u32)
// =================================================================
__global__ void k_splitw(const float* __restrict__ w)   // w: [256][256][9]
{
    int o = blockIdx.x * 256 + threadIdx.x;
    int oc    = o & 63;
    int p     = (o >> 6) & 7;
    int tap   = (o >> 9) % 9;
    int icc   = (o / 4608) & 15;
    int ocblk = o / 73728;
    int ocg = ocblk*64 + oc;
    int ic0 = icc*16 + 2*p;
    __half h0 = __float2half(w[(ocg*C2C + ic0    )*9 + tap]);
    __half h1 = __float2half(w[(ocg*C2C + ic0 + 1)*9 + tap]);
    g_Wq[o] = ((unsigned)__half_as_ushort(h1) << 16) | __half_as_ushort(h0);
    if (o < C2C) { g_bnsum[o] = 0.f; g_bnsq[o] = 0.f; }
}

// =================================================================
// layer-0 prep: v = c2A (fp32 state) + seq2pair(c1); quantize fp16 packed.
// grid 36864 x 256
// =================================================================
__global__ void k_prep0(int csel)
{
    int idx = blockIdx.x * 256 + threadIdx.x;      // 0..BPTOT-1
    int j   = idx % NN;
    int r1  = idx / NN;
    int row = r1 % NN;
    int r2  = r1 / NN;
    int icp = r2 % 128;
    int b   = r2 / 128;
    const float* cc = csel ? g_cB : g_cA;

    int ic0 = icp*2, ic1 = ic0 + 1;
    float x0 = g_c2A[((size_t)(b*C2C + ic0)*NN + row)*NN + j]
             + ((ic0 < DIMD) ? cc[(b*DIMD + ic0)*NN + row]
                             : cc[(b*DIMD + ic0 - DIMD)*NN + j]);
    float x1 = g_c2A[((size_t)(b*C2C + ic1)*NN + row)*NN + j]
             + ((ic1 < DIMD) ? cc[(b*DIMD + ic1)*NN + row]
                             : cc[(b*DIMD + ic1 - DIMD)*NN + j]);

    __half h0 = __float2half(x0);
    __half h1 = __float2half(x1);
    g_Bh[idx] = ((unsigned)__half_as_ushort(h1) << 16) | __half_as_ushort(h0);
}

// =================================================================
// conv2d 3x3 C2->C2 on tensor cores (fp16 1-term, mma.m16n8k16).
// Input in g_Bh (fp16 packed), weights in g_Wq.  fp16 out -> g_c2H.
// Epilogue accumulates per-oc fp32 sum/sumsq into g_bnsum/g_bnsq.
// CTA: 64 oc x output row i x batch.  8 warps: 32 oc x 48 j each.
// =================================================================
#define MMA_F16(c0,c1,c2,c3, A0,A1,A2,A3, B0,B1)                          \
  asm volatile("mma.sync.aligned.m16n8k16.row.col.f32.f16.f16.f32 "       \
    "{%0,%1,%2,%3},{%4,%5,%6,%7},{%8,%9},{%0,%1,%2,%3};"                  \
    : "+f"(c0),"+f"(c1),"+f"(c2),"+f"(c3)                                 \
    : "r"(A0),"r"(A1),"r"(A2),"r"(A3),"r"(B0),"r"(B1))

#define ASZ 5184
#define BSZ 4800
#define CONV_SMEM ((ASZ + BSZ)*4)   // 39936 B

__global__ void __launch_bounds__(256, 2)
k_conv2d_mma()
{
    extern __shared__ unsigned smu[];
    unsigned* Aq = smu;
    unsigned* Bq = smu + ASZ;
    __shared__ float sS[64], sQ[64];

    int ocblk = blockIdx.x;       // 0..3
    int i     = blockIdx.y;       // 0..191
    int b     = blockIdx.z;       // 0..1
    int t = threadIdx.x;
    int w = t >> 5, lane = t & 31;
    int g = lane >> 2, tig = lane & 3;
    int wm = w & 1, wn = w >> 1;

    if (t < 192) {
        int rr = t / 8, cq = t & 7;
        int col = (cq < 4) ? cq : (192 + cq);
        Bq[rr*200 + col] = 0u;
    }
    if (t < 64) { sS[t] = 0.f; sQ[t] = 0.f; }

    float acc[2][6][4];
    #pragma unroll
    for (int m = 0; m < 2; ++m)
        #pragma unroll
        for (int u = 0; u < 6; ++u)
            #pragma unroll
            for (int q = 0; q < 4; ++q) acc[m][u][q] = 0.f;

    const unsigned* wsrc = g_Wq + ocblk*73728;

    for (int icc = 0; icc < 16; ++icc) {
        #pragma unroll
        for (int q = 0; q < 9; ++q) {
            int sidx = q*256 + t;
            if (sidx < 1152) {
                int s4 = sidx * 4;
                int tap = s4 >> 9, p = (s4 >> 6) & 7, oc = s4 & 63;
                ((uint4*)Aq)[((tap*8 + p)*72 + oc) >> 2] =
                    ((const uint4*)wsrc)[icc*1152 + sidx];
            } else {
                int s2 = sidx - 1152;
                int seg = s2 / 48, v4 = s2 - seg*48;
                int r = seg >> 3, icp = seg & 7;
                int row = i - 1 + r;
                uint4 val = make_uint4(0u,0u,0u,0u);
                if (row >= 0 && row < NN)
                    val = ((const uint4*)g_Bh)
                            [(size_t)((b*128 + icc*8 + icp)*NN + row)*48 + v4];
                ((uint4*)Bq)[(seg*200 + 4 + v4*4) >> 2] = val;
            }
        }
        __syncthreads();

        #pragma unroll
        for (int r = 0; r < 3; ++r) {
            #pragma unroll
            for (int dj = 0; dj < 3; ++dj) {
                int tap = r*3 + dj;
                unsigned aq[2][4];
                #pragma unroll
                for (int m = 0; m < 2; ++m) {
                    int mb = wm*32 + m*16 + g;
                    aq[m][0] = Aq[(tap*8 + tig    )*72 + mb    ];
                    aq[m][1] = Aq[(tap*8 + tig    )*72 + mb + 8];
                    aq[m][2] = Aq[(tap*8 + tig + 4)*72 + mb    ];
                    aq[m][3] = Aq[(tap*8 + tig + 4)*72 + mb + 8];
                }
                #pragma unroll
                for (int u = 0; u < 6; ++u) {
                    int col = wn*48 + u*8 + g + dj + 3;
                    unsigned b0 = Bq[(r*8 + tig    )*200 + col];
                    unsigned b1 = Bq[(r*8 + tig + 4)*200 + col];
                    #pragma unroll
                    for (int m = 0; m < 2; ++m) {
                        float* c = acc[m][u];
                        MMA_F16(c[0],c[1],c[2],c[3],
                                aq[m][0],aq[m][1],aq[m][2],aq[m][3], b0,b1);
                    }
                }
            }
        }
        __syncthreads();
    }

    // ---- epilogue: fp32 stats, fp16 store ----
    #pragma unroll
    for (int m = 0; m < 2; ++m) {
        int oc0 = ocblk*64 + wm*32 + m*16 + g;
        float s0 = 0.f, q0 = 0.f, s1 = 0.f, q1 = 0.f;
        #pragma unroll
        for (int u = 0; u < 6; ++u) {
            int j = wn*48 + u*8 + 2*tig;
            float a0 = acc[m][u][0], a1 = acc[m][u][1];
            float a2 = acc[m][u][2], a3 = acc[m][u][3];
            s0 += a0 + a1;  q0 += a0*a0 + a1*a1;
            s1 += a2 + a3;  q1 += a2*a2 + a3*a3;
            *(__half2*)&g_c2H[((size_t)(b*C2C + oc0    )*NN + i)*NN + j] =
                __floats2half2_rn(a0, a1);
            *(__half2*)&g_c2H[((size_t)(b*C2C + oc0 + 8)*NN + i)*NN + j] =
                __floats2half2_rn(a2, a3);
        }
        s0 += __shfl_down_sync(0xffffffffu, s0, 2);
        s0 += __shfl_down_sync(0xffffffffu, s0, 1);
        q0 += __shfl_down_sync(0xffffffffu, q0, 2);
        q0 += __shfl_down_sync(0xffffffffu, q0, 1);
        s1 += __shfl_down_sync(0xffffffffu, s1, 2);
        s1 += __shfl_down_sync(0xffffffffu, s1, 1);
        q1 += __shfl_down_sync(0xffffffffu, q1, 2);
        q1 += __shfl_down_sync(0xffffffffu, q1, 1);
        if (tig == 0) {
            int lo = wm*32 + m*16 + g;
            atomicAdd(&sS[lo    ], s0);
            atomicAdd(&sQ[lo    ], q0);
            atomicAdd(&sS[lo + 8], s1);
            atomicAdd(&sQ[lo + 8], q1);
        }
    }
    __syncthreads();
    if (t < 64) {
        atomicAdd(&g_bnsum[ocblk*64 + t], sS[t]);
        atomicAdd(&g_bnsq [ocblk*64 + t], sQ[t]);
    }
}

// =================================================================
// BN finalize (1 block, 256 threads)
// =================================================================
__global__ void k_bnfin(const float* __restrict__ gg, const float* __restrict__ bb)
{
    int oc = threadIdx.x;
    float mean = g_bnsum[oc] * (1.f / (NB*NSP));
    float var  = g_bnsq[oc] * (1.f / (NB*NSP)) - mean*mean;
    float inv  = rsqrtf(var + 1e-5f);
    float sc = inv * gg[oc];
    g_scale[oc] = sc;
    g_shift[oc] = bb[oc] - mean * sc;
}

// =================================================================
// fused gate + next-layer prep: single pass over g_c2H.
//   v      = relu(bn(c2H[b,c,i,j]))            (current layer state)
//   gate:    G[b,h,i,j] = sum_c v * wd[h,c]
//   prep:    if !last:  g_Bh <- fp16(v + seq2pair(c_next))
// block = (i, b), 192 threads (j).
// =================================================================
__global__ void __launch_bounds__(192)
k_gateprep(int csel, int last, const float* __restrict__ wd)
{
    int i = blockIdx.x, b = blockIdx.y, j = threadIdx.x;
    const float* cc = csel ? g_cB : g_cA;

    __shared__ float wsh[C2C*HH];     // [c][h]
    __shared__ float scs[C2C], shs[C2C], cro[DIMD];
    for (int s = j; s < C2C*HH; s += NN) {
        int c = s >> 3, h = s & 7;
        wsh[s] = wd[h*C2C + c];
    }
    for (int s = j; s < C2C; s += NN) { scs[s] = g_scale[s]; shs[s] = g_shift[s]; }
    if (!last)
        for (int s = j; s < DIMD; s += NN) cro[s] = cc[(b*DIMD + s)*NN + i];
    __syncthreads();

    float acc[HH] = {};
    const __half* base = g_c2H + (size_t)(b*C2C)*NSP + i*NN + j;
    unsigned short prevh = 0;

    #pragma unroll 2
    for (int c = 0; c < C2C; ++c) {
        float v = fmaxf(fmaf(__half2float(base[(size_t)c*NSP]), scs[c], shs[c]), 0.f);
        #pragma unroll
        for (int h = 0; h < HH; ++h) acc[h] += v * wsh[c*8 + h];
        if (!last) {
            float p = v + ((c < DIMD) ? cro[c] : cc[(b*DIMD + c - DIMD)*NN + j]);
            unsigned short curh = __half_as_ushort(__float2half(p));
            if (c & 1)
                g_Bh[((size_t)(b*128 + (c >> 1))*NN + i)*NN + j] =
                    ((unsigned)curh << 16) | prevh;
            else prevh = curh;
        }
    }
    #pragma unroll
    for (int h = 0; h < HH; ++h)
        g_G[((b*HH + h)*NN + i)*NN + j] = acc[h];
}

// =================================================================
// Generic 384x128x128 GEMM with relu epilogue.
// =================================================================
__global__ void k_gemm64(int asel, int addupd,
                         const float* __restrict__ W,
                         const float* __restrict__ bias,
                         int outsel, float* dptr)
{
    __shared__ float As[32*68];
    __shared__ float Ws[32*68];
    int t = threadIdx.x;
    int tx = t & 15, ty = t >> 4;
    int rowbase = blockIdx.y * 64, colbase = blockIdx.x * 64;

    const float* A = asel ? g_xB : g_xA;
    float* outp;
    if      (outsel == 3) { outp = g_xA; }
    else if (outsel == 4) { outp = g_xB; }
    else                  { outp = dptr; }

    float acc[4][4] = {};
    for (int kk = 0; kk < 128; kk += 32) {
        #pragma unroll
        for (int r = 0; r < 8; ++r) {
            int s = r*256 + t;
            int row = s >> 5, e = s & 31;
            float v = A[(rowbase + row)*DIMD + kk + e];
            if (addupd) v += g_upd[(rowbase + row)*DIMD + kk + e];
            As[e*68 + row] = v;
            Ws[e*68 + row] = W[(colbase + row)*DIMD + kk + e];
        }
        __syncthreads();
        #pragma unroll
        for (int e = 0; e < 32; ++e) {
            float a0 = As[e*68 + ty*4 + 0], a1 = As[e*68 + ty*4 + 1];
            float a2 = As[e*68 + ty*4 + 2], a3 = As[e*68 + ty*4 + 3];
            float w0 = Ws[e*68 + tx*4 + 0], w1 = Ws[e*68 + tx*4 + 1];
            float w2 = Ws[e*68 + tx*4 + 2], w3 = Ws[e*68 + tx*4 + 3];
            acc[0][0] += a0*w0; acc[0][1] += a0*w1; acc[0][2] += a0*w2; acc[0][3] += a0*w3;
            acc[1][0] += a1*w0; acc[1][1] += a1*w1; acc[1][2] += a1*w2; acc[1][3] += a1*w3;
            acc[2][0] += a2*w0; acc[2][1] += a2*w1; acc[2][2] += a2*w2; acc[2][3] += a2*w3;
            acc[3][0] += a3*w0; acc[3][1] += a3*w1; acc[3][2] += a3*w2; acc[3][3] += a3*w3;
        }
        __syncthreads();
    }

    #pragma unroll
    for (int v = 0; v < 4; ++v) {
        int row = rowbase + ty*4 + v;
        #pragma unroll
        for (int u = 0; u < 4; ++u) {
            int col = colbase + tx*4 + u;
            float r = fmaxf(acc[v][u] + bias[col], 0.f);
            outp[row*DIMD + col] = r;
        }
    }
}

// =================================================================
// fused q/k/v GEMM: one launch, 3 weight sets; grid (6, 6).
// =================================================================
__global__ void k_gemm_qkv(int asel,
                           const float* __restrict__ Wq, const float* __restrict__ bq,
                           const float* __restrict__ Wk, const float* __restrict__ bk,
                           const float* __restrict__ Wv, const float* __restrict__ bv)
{
    __shared__ float As[32*68];
    __shared__ float Ws[32*68];
    int t = threadIdx.x;
    int tx = t & 15, ty = t >> 4;
    int sel = blockIdx.x >> 1;
    int rowbase = blockIdx.y * 64, colbase = (blockIdx.x & 1) * 64;

    const float* A = asel ? g_xB : g_xA;
    const float* W    = (sel == 0) ? Wq : (sel == 1) ? Wk : Wv;
    const float* bias = (sel == 0) ? bq : (sel == 1) ? bk : bv;
    float* outp       = (sel == 0) ? g_q : (sel == 1) ? g_k : g_v;

    float acc[4][4] = {};
    for (int kk = 0; kk < 128; kk += 32) {
        #pragma unroll
        for (int r = 0; r < 8; ++r) {
            int s = r*256 + t;
            int row = s >> 5, e = s & 31;
            As[e*68 + row] = A[(rowbase + row)*DIMD + kk + e];
            Ws[e*68 + row] = W[(colbase + row)*DIMD + kk + e];
        }
        __syncthreads();
        #pragma unroll
        for (int e = 0; e < 32; ++e) {
            float a0 = As[e*68 + ty*4 + 0], a1 = As[e*68 + ty*4 + 1];
            float a2 = As[e*68 + ty*4 + 2], a3 = As[e*68 + ty*4 + 3];
            float w0 = Ws[e*68 + tx*4 + 0], w1 = Ws[e*68 + tx*4 + 1];
            float w2 = Ws[e*68 + tx*4 + 2], w3 = Ws[e*68 + tx*4 + 3];
            acc[0][0] += a0*w0; acc[0][1] += a0*w1; acc[0][2] += a0*w2; acc[0][3] += a0*w3;
            acc[1][0] += a1*w0; acc[1][1] += a1*w1; acc[1][2] += a1*w2; acc[1][3] += a1*w3;
            acc[2][0] += a2*w0; acc[2][1] += a2*w1; acc[2][2] += a2*w2; acc[2][3] += a2*w3;
            acc[3][0] += a3*w0; acc[3][1] += a3*w1; acc[3][2] += a3*w2; acc[3][3] += a3*w3;
        }
        __syncthreads();
    }

    #pragma unroll
    for (int v = 0; v < 4; ++v) {
        int row = rowbase + ty*4 + v;
        #pragma unroll
        for (int u = 0; u < 4; ++u) {
            int col = colbase + tx*4 + u;
            float r = fmaxf(acc[v][u] + bias[col], 0.f);
            int b = row / NN, n = row % NN, h = col >> 4, dh = col & 15;
            outp[((b*HH + h)*NN + n)*DHH + dh] = r;
        }
    }
}

// =================================================================
// Attention + gate
// =================================================================
__global__ void k_attn(const float* __restrict__ mask,
                       const float* __restrict__ wdb)
{
    int i = blockIdx.x, h = blockIdx.y, b = blockIdx.z;
    int t = threadIdx.x;
    int bh = b*HH + h;

    __shared__ float qi[DHH];
    __shared__ float att[NN];
    __shared__ float redm[8];
    __shared__ float reds[8];
    __shared__ float part[16][17];

    if (t < DHH) qi[t] = g_q[(bh*NN + i)*DHH + t];
    __syncthreads();

    float aval = 0.f;
    if (t < NN) {
        const float* kp = g_k + (bh*NN + t)*DHH;
        float s = 0.f;
        #pragma unroll
        for (int d = 0; d < DHH; ++d) s += qi[d] * kp[d];
        aval = s * 0.25f;
    }
    float mval = (t < NN) ? aval : -3e38f;
    #pragma unroll
    for (int o = 16; o; o >>= 1) mval = fmaxf(mval, __shfl_xor_sync(0xffffffffu, mval, o));
    if (!(t & 31)) redm[t >> 5] = mval;
    __syncthreads();
    float mx = redm[0];
    #pragma unroll
    for (int ww = 1; ww < 8; ++ww) mx = fmaxf(mx, redm[ww]);

    float e = (t < NN) ? expf(aval - mx) * mask[b*NN + t] : 0.f;
    float sv = e;
    #pragma unroll
    for (int o = 16; o; o >>= 1) sv += __shfl_xor_sync(0xffffffffu, sv, o);
    if (!(t & 31)) reds[t >> 5] = sv;
    __syncthreads();
    float den = 1e-6f;
    #pragma unroll
    for (int ww = 0; ww < 8; ++ww) den += reds[ww];

    if (t < NN) {
        float gl = g_G[(bh*NN + i)*NN + t] + g_G[(bh*NN + t)*NN + i] + wdb[h];
        float gate = 1.f / (1.f + expf(-gl));
        att[t] = (e / den) * gate;
    }
    __syncthreads();

    int d = t & 15, grp = t >> 4;
    float p = 0.f;
    #pragma unroll
    for (int jj = 0; jj < 12; ++jj) {
        int j = grp*12 + jj;
        p += att[j] * g_v[(bh*NN + j)*DHH + d];
    }
    part[grp][d] = p;
    __syncthreads();
    if (t < DHH) {
        float s = 0.f;
        #pragma unroll
        for (int gg = 0; gg < 16; ++gg) s += part[gg][t];
        g_upd[(b*NN + i)*DIMD + h*DHH + t] = s;
    }
}

// =================================================================
// host
// =================================================================
extern "C" void kernel_launch(void* const* d_in, const int* in_sizes, int n_in,
                              void* d_out, int out_size)
{
    const float* seq     = (const float*)d_in[0];
    const float* mask    = (const float*)d_in[1];
    const float* conv1_w = (const float*)d_in[2];
    const float* conv2_w = (const float*)d_in[3];
    const float* ln_g    = (const float*)d_in[4];
    const float* ln_b    = (const float*)d_in[5];
    const float* c1d_w   = (const float*)d_in[6];
    const float* bn1_g   = (const float*)d_in[7];
    const float* bn1_b   = (const float*)d_in[8];
    const float* c2d_w   = (const float*)d_in[9];
    const float* bn2_g   = (const float*)d_in[10];
    const float* bn2_b   = (const float*)d_in[11];
    const float* wq_w    = (const float*)d_in[12];
    const float* wq_b    = (const float*)d_in[13];
    const float* wk_w    = (const float*)d_in[14];
    const float* wk_b    = (const float*)d_in[15];
    const float* wv_w    = (const float*)d_in[16];
    const float* wv_b    = (const float*)d_in[17];
    const float* wd_w    = (const float*)d_in[18];
    const float* wd_b    = (const float*)d_in[19];
    const float* wl_w    = (const float*)d_in[20];
    const float* wl_b    = (const float*)d_in[21];
    const float* fc_w    = (const float*)d_in[22];
    const float* fc_b    = (const float*)d_in[23];
    float* out = (float*)d_out;

    static int smem_set = 0;
    if (!smem_set) {
        cudaFuncSetAttribute(k_conv2d_mma, cudaFuncAttributeMaxDynamicSharedMemorySize, CONV_SMEM);
        smem_set = 1;
    }

    k_stem<<<dim3(NN, NB), 128>>>(seq, conv1_w, conv2_w);
    k_pair0<<<C2TOT/256, 256>>>();
    // c1 = conv1bn(c_stem): reads cA, writes cB
    k_conv1bn<<<DIMD, 384>>>(0, c1d_w, bn1_g, bn1_b);

    int xs = 0;
    int cbuf = 1;    // buffer holding c_{l+1} for current layer l
    for (int l = 0; l < 3; ++l) {
        k_ln<<<dim3(NN, NB), DIMD>>>(xs, cbuf, ln_g + l*DIMD, ln_b + l*DIMD);
        k_splitw<<<1152, 256>>>(c2d_w + l*C2C*C2C*9);
        if (l == 0) k_prep0<<<BPTOT/256, 256>>>(cbuf);
        k_conv2d_mma<<<dim3(4, NN, NB), 256, CONV_SMEM>>>();
        k_bnfin<<<1, 256>>>(bn2_g + l*C2C, bn2_b + l*C2C);
        if (l < 2)   // compute c_{l+2} early (depends only on c_{l+1})
            k_conv1bn<<<DIMD, 384>>>(cbuf, c1d_w + (l+1)*DIMD*DIMD*3,
                                     bn1_g + (l+1)*DIMD, bn1_b + (l+1)*DIMD);
        k_gateprep<<<dim3(NN, NB), 192>>>(cbuf ^ 1, l == 2 ? 1 : 0, wd_w + l*HH*C2C);
        k_gemm_qkv<<<dim3(6, 6), 256>>>(xs, wq_w + l*DIMD*DIMD, wq_b + l*DIMD,
                                            wk_w + l*DIMD*DIMD, wk_b + l*DIMD,
                                            wv_w + l*DIMD*DIMD, wv_b + l*DIMD);
        k_attn<<<dim3(NN, HH, NB), 256>>>(mask, wd_b + l*HH);
        k_gemm64<<<dim3(2, 6), 256>>>(xs, 1, wl_w + l*DIMD*DIMD, wl_b + l*DIMD, xs ? 3 : 4, nullptr);
        cbuf ^= 1;
        xs ^= 1;
    }
    k_gemm64<<<dim3(2, 6), 256>>>(xs, 0, fc_w, fc_b, 5, out);
}

// round 17
// speedup vs baseline: 5.2238x; 1.0672x over previous
#include <cuda_runtime.h>
#include <cuda_fp16.h>
#include <cstdint>

// ---------------- problem constants ----------------
#define NB   2
#define NN   192
#define IND  20
#define DIMD 128
#define HH   8
#define DHH  16
#define C2C  256
#define NSP  (NN*NN)            // 36864
#define C2TOT (NB*C2C*NSP)      // 18874368

// ---------------- scratch (device globals; no allocation allowed) ----------------
__device__ float g_xA[NB*NN*DIMD];
__device__ float g_xB[NB*NN*DIMD];
__device__ float g_cA[NB*DIMD*NN];
__device__ float g_cB[NB*DIMD*NN];
__device__ float g_q[NB*HH*NN*DHH];
__device__ float g_k[NB*HH*NN*DHH];
__device__ float g_v[NB*HH*NN*DHH];
__device__ float g_upd[NB*NN*DIMD];
__device__ float g_G[NB*HH*NSP];
__device__ float g_bnsum[C2C];
__device__ float g_bnsq[C2C];
__device__ __half g_c2H[C2TOT];    // raw conv2d output (pre-BN), fp16
// fp16 conv weights packed (ic even | ic odd<<16): [ocblk4][icc16][tap9][icpair8][oc64]
__device__ unsigned g_Wq[C2C*C2C*9/2];
// fp16 conv input packed by ic-pair: [b2][icpair128][row192][j192]
#define BPTOT (NB*128*NN*NN)    // 9437184
__device__ unsigned g_Bh[BPTOT];

// =================================================================
// Stem: x = conv1d(seq^T, conv1_w)^T ; c = conv1d(seq^T, conv2_w)
// =================================================================
__global__ void k_stem(const float* __restrict__ seq,
                       const float* __restrict__ w1,
                       const float* __restrict__ w2)
{
    int n = blockIdx.x, b = blockIdx.y, d = threadIdx.x;
    __shared__ float s3[3][IND];
    if (d < 3*IND) {
        int r = d / IND, ic = d % IND;
        int nn = n - 1 + r;
        s3[r][ic] = (nn >= 0 && nn < NN) ? seq[(b*NN + nn)*IND + ic] : 0.f;
    }
    __syncthreads();
    float ax = 0.f, ac = 0.f;
    #pragma unroll
    for (int ic = 0; ic < IND; ++ic) {
        #pragma unroll
        for (int r = 0; r < 3; ++r) {
            float v = s3[r][ic];
            ax += v * w1[(d*IND + ic)*3 + r];
            ac += v * w2[(d*IND + ic)*3 + r];
        }
    }
    g_xA[(b*NN + n)*DIMD + d] = ax;
    g_cA[(b*DIMD + d)*NN + n] = ac;
}

// =================================================================
// c = relu(bn1(conv1d(c, c1d_w[l])))  — chunked smem staging.
// rd: reads rd?cB:cA, writes the other.
// =================================================================
__global__ void __launch_bounds__(384)
k_conv1bn(int rd, const float* __restrict__ w,
          const float* __restrict__ gg, const float* __restrict__ bb)
{
    int d = blockIdx.x;
    int t = threadIdx.x;
    int b = t / NN, n = t % NN;
    const float* c  = rd ? g_cB : g_cA;
    float*       co = rd ? g_cA : g_cB;

    __shared__ float sc[16][2][194];
    __shared__ float wsh[DIMD*3];
    __shared__ float red[2][12];

    wsh[t] = w[d*DIMD*3 + t];
    if (t < 32) { sc[t >> 1][t & 1][0] = 0.f; sc[t >> 1][t & 1][193] = 0.f; }
    __syncthreads();

    float acc = 0.f;
    for (int ec = 0; ec < DIMD; ec += 16) {
        #pragma unroll
        for (int q = 0; q < 16; ++q) {
            int s = q*384 + t;
            int e1 = s / 384;
            int rem = s - e1*384;
            int bb2 = rem / NN, n2 = rem - bb2*NN;
            sc[e1][bb2][n2 + 1] = c[((bb2*DIMD) + ec + e1)*NN + n2];
        }
        __syncthreads();
        #pragma unroll
        for (int e1 = 0; e1 < 16; ++e1) {
            int e = ec + e1;
            acc += sc[e1][b][n]     * wsh[e*3 + 0]
                 + sc[e1][b][n + 1] * wsh[e*3 + 1]
                 + sc[e1][b][n + 2] * wsh[e*3 + 2];
        }
        __syncthreads();
    }

    float s = acc, ss = acc * acc;
    #pragma unroll
    for (int o = 16; o; o >>= 1) {
        s  += __shfl_down_sync(0xffffffffu, s,  o);
        ss += __shfl_down_sync(0xffffffffu, ss, o);
    }
    if (!(t & 31)) { red[0][t >> 5] = s; red[1][t >> 5] = ss; }
    __syncthreads();
    float ts = 0.f, tss = 0.f;
    #pragma unroll
    for (int ww = 0; ww < 12; ++ww) { ts += red[0][ww]; tss += red[1][ww]; }
    float mean = ts * (1.f/384.f);
    float var  = tss * (1.f/384.f) - mean*mean;
    float inv  = rsqrtf(var + 1e-5f);

    float outv = fmaxf((acc - mean) * inv * gg[d] + bb[d], 0.f);
    co[(b*DIMD + d)*NN + n] = outv;
}

// =================================================================
// x = LN(x + c^T)
// =================================================================
__global__ void k_ln(int xs, int cs,
                     const float* __restrict__ gg, const float* __restrict__ bb)
{
    int n = blockIdx.x, b = blockIdx.y, d = threadIdx.x;
    float*       x = xs ? g_xB : g_xA;
    const float* c = cs ? g_cB : g_cA;

    float v = x[(b*NN + n)*DIMD + d] + c[(b*DIMD + d)*NN + n];

    __shared__ float red[2][4];
    float s = v, ss = v*v;
    #pragma unroll
    for (int o = 16; o; o >>= 1) {
        s  += __shfl_down_sync(0xffffffffu, s,  o);
        ss += __shfl_down_sync(0xffffffffu, ss, o);
    }
    if (!(d & 31)) { red[0][d >> 5] = s; red[1][d >> 5] = ss; }
    __syncthreads();
    float m   = (red[0][0]+red[0][1]+red[0][2]+red[0][3]) * (1.f/128.f);
    float var = (red[1][0]+red[1][1]+red[1][2]+red[1][3]) * (1.f/128.f) - m*m;
    float inv = rsqrtf(var + 1e-5f);
    x[(b*NN + n)*DIMD + d] = (v - m) * inv * gg[d] + bb[d];
}

// =================================================================
// conv2d weights -> single fp16, packed pairs along ic; also zeros BN accum.
// grid = 1152 x 256 (294912 u32)
// =================================================================
__global__ void k_splitw(const float* __restrict__ w)   // w: [256][256][9]
{
    int o = blockIdx.x * 256 + threadIdx.x;
    int oc    = o & 63;
    int p     = (o >> 6) & 7;
    int tap   = (o >> 9) % 9;
    int icc   = (o / 4608) & 15;
    int ocblk = o / 73728;
    int ocg = ocblk*64 + oc;
    int ic0 = icc*16 + 2*p;
    __half h0 = __float2half(w[(ocg*C2C + ic0    )*9 + tap]);
    __half h1 = __float2half(w[(ocg*C2C + ic0 + 1)*9 + tap]);
    g_Wq[o] = ((unsigned)__half_as_ushort(h1) << 16) | __half_as_ushort(h0);
    if (o < C2C) { g_bnsum[o] = 0.f; g_bnsq[o] = 0.f; }
}

// =================================================================
// layer-0 prep: seq2pair is linear, so input = seq2pair(c_stem + c1)
// with c_stem in cA, c1 in cB.  fp16 packed -> g_Bh.
// grid 36864 x 256
// =================================================================
__global__ void k_prep0()
{
    int idx = blockIdx.x * 256 + threadIdx.x;      // 0..BPTOT-1
    int j   = idx % NN;
    int r1  = idx / NN;
    int row = r1 % NN;
    int r2  = r1 / NN;
    int icp = r2 % 128;
    int b   = r2 / 128;

    int ic0 = icp*2, ic1 = ic0 + 1;
    int p0 = (ic0 < DIMD) ? ((b*DIMD + ic0)*NN + row) : ((b*DIMD + ic0 - DIMD)*NN + j);
    int p1 = (ic1 < DIMD) ? ((b*DIMD + ic1)*NN + row) : ((b*DIMD + ic1 - DIMD)*NN + j);
    float x0 = g_cA[p0] + g_cB[p0];
    float x1 = g_cA[p1] + g_cB[p1];

    __half h0 = __float2half(x0);
    __half h1 = __float2half(x1);
    g_Bh[idx] = ((unsigned)__half_as_ushort(h1) << 16) | __half_as_ushort(h0);
}

// =================================================================
// conv2d 3x3 C2->C2 on tensor cores (fp16, mma.m16n8k16), v2:
// 512 threads, 2 output rows per CTA, ping-pong smem, reg prefetch.
// grid (4 ocblk, 96 row-pairs, 2 b).  16 warps: (wm2 x wn4 x wr2),
// warp tile 32 oc x 48 j on row i0+wr.
// Smem per buffer: Aq [tap9][icpair8][stride 72] (5184)
//                  Bq [rowlocal4*icp8 = 32 segs][stride 200] (6400)
// =================================================================
#define MMA_F16(c0,c1,c2,c3, A0,A1,A2,A3, B0,B1)                          \
  asm volatile("mma.sync.aligned.m16n8k16.row.col.f32.f16.f16.f32 "       \
    "{%0,%1,%2,%3},{%4,%5,%6,%7},{%8,%9},{%0,%1,%2,%3};"                  \
    : "+f"(c0),"+f"(c1),"+f"(c2),"+f"(c3)                                 \
    : "r"(A0),"r"(A1),"r"(A2),"r"(A3),"r"(B0),"r"(B1))

#define ASZ2 5184
#define BSZ2 6400
#define PP   (ASZ2 + BSZ2)          // 11584 u32 per buffer
#define NSLOT 2688                  // 1152 A + 1536 B uint4 per chunk
#define CONV_SMEM (2*PP*4)          // 92672 B

__device__ __forceinline__ void ldg_chunk(int icc, int i0, int b,
                                          const uint4* __restrict__ wsrc4,
                                          uint4* pre, int t)
{
    #pragma unroll
    for (int q = 0; q < 6; ++q) {
        int s = q*512 + t;
        if (s >= NSLOT) continue;
        if (s < 1152) {
            pre[q] = wsrc4[icc*1152 + s];
        } else {
            int s2 = s - 1152;
            int seg = s2 / 48, v4 = s2 - seg*48;
            int rowl = seg >> 3, icp = seg & 7;
            int grow = i0 - 1 + rowl;
            uint4 val = make_uint4(0u,0u,0u,0u);
            if (grow >= 0 && grow < NN)
                val = ((const uint4*)g_Bh)
                        [(size_t)((b*128 + icc*8 + icp)*NN + grow)*48 + v4];
            pre[q] = val;
        }
    }
}

__device__ __forceinline__ void sts_chunk(unsigned* base, const uint4* pre, int t)
{
    #pragma unroll
    for (int q = 0; q < 6; ++q) {
        int s = q*512 + t;
        if (s >= NSLOT) continue;
        int d;
        if (s < 1152) {
            int s4 = s*4;
            int tap = s4 >> 9, p = (s4 >> 6) & 7, oc = s4 & 63;
            d = (tap*8 + p)*72 + oc;
        } else {
            int s2 = s - 1152;
            int seg = s2 / 48, v4 = s2 - seg*48;
            d = ASZ2 + seg*200 + 4 + v4*4;
        }
        ((uint4*)base)[d >> 2] = pre[q];
    }
}

__global__ void __launch_bounds__(512, 1)
k_conv2d_mma()
{
    extern __shared__ unsigned smu[];
    __shared__ float sS[64], sQ[64];

    int ocblk = blockIdx.x;       // 0..3
    int ip    = blockIdx.y;       // 0..95
    int b     = blockIdx.z;       // 0..1
    int i0 = ip*2;
    int t = threadIdx.x;
    int w = t >> 5, lane = t & 31;
    int g = lane >> 2, tig = lane & 3;
    int wm = w & 1, wn = (w >> 1) & 3, wr = w >> 3;
    int i = i0 + wr;

    // zero B halo cols for BOTH buffers: 2 buf x 32 segs x 8 cols = 512 exact
    {
        int buf = t >> 8;
        int r2 = t & 255;
        int rr = r2 >> 3, cq = r2 & 7;
        int col = (cq < 4) ? cq : (192 + cq);
        smu[buf*PP + ASZ2 + rr*200 + col] = 0u;
    }
    if (t < 64) { sS[t] = 0.f; sQ[t] = 0.f; }

    float acc[2][6][4];
    #pragma unroll
    for (int m = 0; m < 2; ++m)
        #pragma unroll
        for (int u = 0; u < 6; ++u)
            #pragma unroll
            for (int q = 0; q < 4; ++q) acc[m][u][q] = 0.f;

    const uint4* wsrc4 = (const uint4*)(g_Wq + ocblk*73728);

    uint4 pre[6];
    ldg_chunk(0, i0, b, wsrc4, pre, t);

    for (int icc = 0; icc < 16; ++icc) {
        unsigned* base = smu + (icc & 1)*PP;
        sts_chunk(base, pre, t);
        __syncthreads();
        if (icc < 15) ldg_chunk(icc + 1, i0, b, wsrc4, pre, t);

        unsigned* Aq = base;
        unsigned* Bq = base + ASZ2;
        #pragma unroll
        for (int r = 0; r < 3; ++r) {
            int segbase = (wr + r)*8;
            #pragma unroll
            for (int dj = 0; dj < 3; ++dj) {
                int tap = r*3 + dj;
                unsigned aq[2][4];
                #pragma unroll
                for (int m = 0; m < 2; ++m) {
                    int mb = wm*32 + m*16 + g;
                    aq[m][0] = Aq[(tap*8 + tig    )*72 + mb    ];
                    aq[m][1] = Aq[(tap*8 + tig    )*72 + mb + 8];
                    aq[m][2] = Aq[(tap*8 + tig + 4)*72 + mb    ];
                    aq[m][3] = Aq[(tap*8 + tig + 4)*72 + mb + 8];
                }
                #pragma unroll
                for (int u = 0; u < 6; ++u) {
                    int col = wn*48 + u*8 + g + dj + 3;
                    unsigned b0 = Bq[(segbase + tig    )*200 + col];
                    unsigned b1 = Bq[(segbase + tig + 4)*200 + col];
                    #pragma unroll
                    for (int m = 0; m < 2; ++m) {
                        float* c = acc[m][u];
                        MMA_F16(c[0],c[1],c[2],c[3],
                                aq[m][0],aq[m][1],aq[m][2],aq[m][3], b0,b1);
                    }
                }
            }
        }
    }

    // ---- epilogue: fp16 store + per-oc fp32 stats ----
    #pragma unroll
    for (int m = 0; m < 2; ++m) {
        int oc0 = ocblk*64 + wm*32 + m*16 + g;
        float s0 = 0.f, q0 = 0.f, s1 = 0.f, q1 = 0.f;
        #pragma unroll
        for (int u = 0; u < 6; ++u) {
            int j = wn*48 + u*8 + 2*tig;
            float a0 = acc[m][u][0], a1 = acc[m][u][1];
            float a2 = acc[m][u][2], a3 = acc[m][u][3];
            s0 += a0 + a1;  q0 += a0*a0 + a1*a1;
            s1 += a2 + a3;  q1 += a2*a2 + a3*a3;
            *(__half2*)&g_c2H[((size_t)(b*C2C + oc0    )*NN + i)*NN + j] =
                __floats2half2_rn(a0, a1);
            *(__half2*)&g_c2H[((size_t)(b*C2C + oc0 + 8)*NN + i)*NN + j] =
                __floats2half2_rn(a2, a3);
        }
        s0 += __shfl_down_sync(0xffffffffu, s0, 2);
        s0 += __shfl_down_sync(0xffffffffu, s0, 1);
        q0 += __shfl_down_sync(0xffffffffu, q0, 2);
        q0 += __shfl_down_sync(0xffffffffu, q0, 1);
        s1 += __shfl_down_sync(0xffffffffu, s1, 2);
        s1 += __shfl_down_sync(0xffffffffu, s1, 1);
        q1 += __shfl_down_sync(0xffffffffu, q1, 2);
        q1 += __shfl_down_sync(0xffffffffu, q1, 1);
        if (tig == 0) {
            int lo = wm*32 + m*16 + g;
            atomicAdd(&sS[lo    ], s0);
            atomicAdd(&sQ[lo    ], q0);
            atomicAdd(&sS[lo + 8], s1);
            atomicAdd(&sQ[lo + 8], q1);
        }
    }
    __syncthreads();
    if (t < 64) {
        atomicAdd(&g_bnsum[ocblk*64 + t], sS[t]);
        atomicAdd(&g_bnsq [ocblk*64 + t], sQ[t]);
    }
}

// =================================================================
// fused BN-finalize + gate + next-layer prep: single pass over g_c2H.
//   scale/shift derived in-block from g_bnsum/g_bnsq (bnfin folded in).
//   v = relu(bn(c2H));  G[b,h,i,j] = sum_c v*wd[h,c];
//   if !last: g_Bh <- fp16(v + seq2pair(c_next))
// block = (i, b), 192 threads (j).
// =================================================================
__global__ void __launch_bounds__(192)
k_gateprep(int csel, int last, const float* __restrict__ wd,
           const float* __restrict__ gg, const float* __restrict__ bb)
{
    int i = blockIdx.x, b = blockIdx.y, j = threadIdx.x;
    const float* cc = csel ? g_cB : g_cA;

    __shared__ float wsh[C2C*HH];     // [c][h]
    __shared__ float scs[C2C], shs[C2C], cro[DIMD];
    for (int s = j; s < C2C*HH; s += NN) {
        int c = s >> 3, h = s & 7;
        wsh[s] = wd[h*C2C + c];
    }
    for (int s = j; s < C2C; s += NN) {
        float mean = g_bnsum[s] * (1.f / (NB*NSP));
        float var  = g_bnsq[s] * (1.f / (NB*NSP)) - mean*mean;
        float inv  = rsqrtf(var + 1e-5f);
        float sc = inv * gg[s];
        scs[s] = sc;
        shs[s] = bb[s] - mean * sc;
    }
    if (!last)
        for (int s = j; s < DIMD; s += NN) cro[s] = cc[(b*DIMD + s)*NN + i];
    __syncthreads();

    float acc[HH] = {};
    const __half* base = g_c2H + (size_t)(b*C2C)*NSP + i*NN + j;
    unsigned short prevh = 0;

    #pragma unroll 2
    for (int c = 0; c < C2C; ++c) {
        float v = fmaxf(fmaf(__half2float(base[(size_t)c*NSP]), scs[c], shs[c]), 0.f);
        #pragma unroll
        for (int h = 0; h < HH; ++h) acc[h] += v * wsh[c*8 + h];
        if (!last) {
            float p = v + ((c < DIMD) ? cro[c] : cc[(b*DIMD + c - DIMD)*NN + j]);
            unsigned short curh = __half_as_ushort(__float2half(p));
            if (c & 1)
                g_Bh[((size_t)(b*128 + (c >> 1))*NN + i)*NN + j] =
                    ((unsigned)curh << 16) | prevh;
            else prevh = curh;
        }
    }
    #pragma unroll
    for (int h = 0; h < HH; ++h)
        g_G[((b*HH + h)*NN + i)*NN + j] = acc[h];
}

// =================================================================
// Generic 384x128x128 GEMM with relu epilogue.
// =================================================================
__global__ void k_gemm64(int asel, int addupd,
                         const float* __restrict__ W,
                         const float* __restrict__ bias,
                         int outsel, float* dptr)
{
    __shared__ float As[32*68];
    __shared__ float Ws[32*68];
    int t = threadIdx.x;
    int tx = t & 15, ty = t >> 4;
    int rowbase = blockIdx.y * 64, colbase = blockIdx.x * 64;

    const float* A = asel ? g_xB : g_xA;
    float* outp;
    if      (outsel == 3) { outp = g_xA; }
    else if (outsel == 4) { outp = g_xB; }
    else                  { outp = dptr; }

    float acc[4][4] = {};
    for (int kk = 0; kk < 128; kk += 32) {
        #pragma unroll
        for (int r = 0; r < 8; ++r) {
            int s = r*256 + t;
            int row = s >> 5, e = s & 31;
            float v = A[(rowbase + row)*DIMD + kk + e];
            if (addupd) v += g_upd[(rowbase + row)*DIMD + kk + e];
            As[e*68 + row] = v;
            Ws[e*68 + row] = W[(colbase + row)*DIMD + kk + e];
        }
        __syncthreads();
        #pragma unroll
        for (int e = 0; e < 32; ++e) {
            float a0 = As[e*68 + ty*4 + 0], a1 = As[e*68 + ty*4 + 1];
            float a2 = As[e*68 + ty*4 + 2], a3 = As[e*68 + ty*4 + 3];
            float w0 = Ws[e*68 + tx*4 + 0], w1 = Ws[e*68 + tx*4 + 1];
            float w2 = Ws[e*68 + tx*4 + 2], w3 = Ws[e*68 + tx*4 + 3];
            acc[0][0] += a0*w0; acc[0][1] += a0*w1; acc[0][2] += a0*w2; acc[0][3] += a0*w3;
            acc[1][0] += a1*w0; acc[1][1] += a1*w1; acc[1][2] += a1*w2; acc[1][3] += a1*w3;
            acc[2][0] += a2*w0; acc[2][1] += a2*w1; acc[2][2] += a2*w2; acc[2][3] += a2*w3;
            acc[3][0] += a3*w0; acc[3][1] += a3*w1; acc[3][2] += a3*w2; acc[3][3] += a3*w3;
        }
        __syncthreads();
    }

    #pragma unroll
    for (int v = 0; v < 4; ++v) {
        int row = rowbase + ty*4 + v;
        #pragma unroll
        for (int u = 0; u < 4; ++u) {
            int col = colbase + tx*4 + u;
            float r = fmaxf(acc[v][u] + bias[col], 0.f);
            outp[row*DIMD + col] = r;
        }
    }
}

// =================================================================
// fused q/k/v GEMM: one launch, 3 weight sets; grid (6, 6).
// =================================================================
__global__ void k_gemm_qkv(int asel,
                           const float* __restrict__ Wq, const float* __restrict__ bq,
                           const float* __restrict__ Wk, const float* __restrict__ bk,
                           const float* __restrict__ Wv, const float* __restrict__ bv)
{
    __shared__ float As[32*68];
    __shared__ float Ws[32*68];
    int t = threadIdx.x;
    int tx = t & 15, ty = t >> 4;
    int sel = blockIdx.x >> 1;
    int rowbase = blockIdx.y * 64, colbase = (blockIdx.x & 1) * 64;

    const float* A = asel ? g_xB : g_xA;
    const float* W    = (sel == 0) ? Wq : (sel == 1) ? Wk : Wv;
    const float* bias = (sel == 0) ? bq : (sel == 1) ? bk : bv;
    float* outp       = (sel == 0) ? g_q : (sel == 1) ? g_k : g_v;

    float acc[4][4] = {};
    for (int kk = 0; kk < 128; kk += 32) {
        #pragma unroll
        for (int r = 0; r < 8; ++r) {
            int s = r*256 + t;
            int row = s >> 5, e = s & 31;
            As[e*68 + row] = A[(rowbase + row)*DIMD + kk + e];
            Ws[e*68 + row] = W[(colbase + row)*DIMD + kk + e];
        }
        __syncthreads();
        #pragma unroll
        for (int e = 0; e < 32; ++e) {
            float a0 = As[e*68 + ty*4 + 0], a1 = As[e*68 + ty*4 + 1];
            float a2 = As[e*68 + ty*4 + 2], a3 = As[e*68 + ty*4 + 3];
            float w0 = Ws[e*68 + tx*4 + 0], w1 = Ws[e*68 + tx*4 + 1];
            float w2 = Ws[e*68 + tx*4 + 2], w3 = Ws[e*68 + tx*4 + 3];
            acc[0][0] += a0*w0; acc[0][1] += a0*w1; acc[0][2] += a0*w2; acc[0][3] += a0*w3;
            acc[1][0] += a1*w0; acc[1][1] += a1*w1; acc[1][2] += a1*w2; acc[1][3] += a1*w3;
            acc[2][0] += a2*w0; acc[2][1] += a2*w1; acc[2][2] += a2*w2; acc[2][3] += a2*w3;
            acc[3][0] += a3*w0; acc[3][1] += a3*w1; acc[3][2] += a3*w2; acc[3][3] += a3*w3;
        }
        __syncthreads();
    }

    #pragma unroll
    for (int v = 0; v < 4; ++v) {
        int row = rowbase + ty*4 + v;
        #pragma unroll
        for (int u = 0; u < 4; ++u) {
            int col = colbase + tx*4 + u;
            float r = fmaxf(acc[v][u] + bias[col], 0.f);
            int b = row / NN, n = row % NN, h = col >> 4, dh = col & 15;
            outp[((b*HH + h)*NN + n)*DHH + dh] = r;
        }
    }
}

// =================================================================
// Attention + gate
// =================================================================
__global__ void k_attn(const float* __restrict__ mask,
                       const float* __restrict__ wdb)
{
    int i = blockIdx.x, h = blockIdx.y, b = blockIdx.z;
    int t = threadIdx.x;
    int bh = b*HH + h;

    __shared__ float qi[DHH];
    __shared__ float att[NN];
    __shared__ float redm[8];
    __shared__ float reds[8];
    __shared__ float part[16][17];

    if (t < DHH) qi[t] = g_q[(bh*NN + i)*DHH + t];
    __syncthreads();

    float aval = 0.f;
    if (t < NN) {
        const float* kp = g_k + (bh*NN + t)*DHH;
        float s = 0.f;
        #pragma unroll
        for (int d = 0; d < DHH; ++d) s += qi[d] * kp[d];
        aval = s * 0.25f;
    }
    float mval = (t < NN) ? aval : -3e38f;
    #pragma unroll
    for (int o = 16; o; o >>= 1) mval = fmaxf(mval, __shfl_xor_sync(0xffffffffu, mval, o));
    if (!(t & 31)) redm[t >> 5] = mval;
    __syncthreads();
    float mx = redm[0];
    #pragma unroll
    for (int ww = 1; ww < 8; ++ww) mx = fmaxf(mx, redm[ww]);

    float e = (t < NN) ? expf(aval - mx) * mask[b*NN + t] : 0.f;
    float sv = e;
    #pragma unroll
    for (int o = 16; o; o >>= 1) sv += __shfl_xor_sync(0xffffffffu, sv, o);
    if (!(t & 31)) reds[t >> 5] = sv;
    __syncthreads();
    float den = 1e-6f;
    #pragma unroll
    for (int ww = 0; ww < 8; ++ww) den += reds[ww];

    if (t < NN) {
        float gl = g_G[(bh*NN + i)*NN + t] + g_G[(bh*NN + t)*NN + i] + wdb[h];
        float gate = 1.f / (1.f + expf(-gl));
        att[t] = (e / den) * gate;
    }
    __syncthreads();

    int d = t & 15, grp = t >> 4;
    float p = 0.f;
    #pragma unroll
    for (int jj = 0; jj < 12; ++jj) {
        int j = grp*12 + jj;
        p += att[j] * g_v[(bh*NN + j)*DHH + d];
    }
    part[grp][d] = p;
    __syncthreads();
    if (t < DHH) {
        float s = 0.f;
        #pragma unroll
        for (int gg = 0; gg < 16; ++gg) s += part[gg][t];
        g_upd[(b*NN + i)*DIMD + h*DHH + t] = s;
    }
}

// =================================================================
// host
// =================================================================
extern "C" void kernel_launch(void* const* d_in, const int* in_sizes, int n_in,
                              void* d_out, int out_size)
{
    const float* seq     = (const float*)d_in[0];
    const float* mask    = (const float*)d_in[1];
    const float* conv1_w = (const float*)d_in[2];
    const float* conv2_w = (const float*)d_in[3];
    const float* ln_g    = (const float*)d_in[4];
    const float* ln_b    = (const float*)d_in[5];
    const float* c1d_w   = (const float*)d_in[6];
    const float* bn1_g   = (const float*)d_in[7];
    const float* bn1_b   = (const float*)d_in[8];
    const float* c2d_w   = (const float*)d_in[9];
    const float* bn2_g   = (const float*)d_in[10];
    const float* bn2_b   = (const float*)d_in[11];
    const float* wq_w    = (const float*)d_in[12];
    const float* wq_b    = (const float*)d_in[13];
    const float* wk_w    = (const float*)d_in[14];
    const float* wk_b    = (const float*)d_in[15];
    const float* wv_w    = (const float*)d_in[16];
    const float* wv_b    = (const float*)d_in[17];
    const float* wd_w    = (const float*)d_in[18];
    const float* wd_b    = (const float*)d_in[19];
    const float* wl_w    = (const float*)d_in[20];
    const float* wl_b    = (const float*)d_in[21];
    const float* fc_w    = (const float*)d_in[22];
    const float* fc_b    = (const float*)d_in[23];
    float* out = (float*)d_out;

    static int smem_set = 0;
    if (!smem_set) {
        cudaFuncSetAttribute(k_conv2d_mma, cudaFuncAttributeMaxDynamicSharedMemorySize, CONV_SMEM);
        smem_set = 1;
    }

    k_stem<<<dim3(NN, NB), 128>>>(seq, conv1_w, conv2_w);
    // c1 = conv1bn(c_stem): reads cA, writes cB
    k_conv1bn<<<DIMD, 384>>>(0, c1d_w, bn1_g, bn1_b);
    k_prep0<<<BPTOT/256, 256>>>();   // input_0 = seq2pair(c_stem + c1)

    int xs = 0;
    int cbuf = 1;    // buffer holding c_{l+1} for current layer l
    for (int l = 0; l < 3; ++l) {
        k_ln<<<dim3(NN, NB), DIMD>>>(xs, cbuf, ln_g + l*DIMD, ln_b + l*DIMD);
        k_splitw<<<1152, 256>>>(c2d_w + l*C2C*C2C*9);
        k_conv2d_mma<<<dim3(4, NN/2, NB), 512, CONV_SMEM>>>();
        if (l < 2)   // compute c_{l+2} early (depends only on c_{l+1})
            k_conv1bn<<<DIMD, 384>>>(cbuf, c1d_w + (l+1)*DIMD*DIMD*3,
                                     bn1_g + (l+1)*DIMD, bn1_b + (l+1)*DIMD);
        k_gateprep<<<dim3(NN, NB), 192>>>(cbuf ^ 1, l == 2 ? 1 : 0,
                                          wd_w + l*HH*C2C,
                                          bn2_g + l*C2C, bn2_b + l*C2C);
        k_gemm_qkv<<<dim3(6, 6), 256>>>(xs, wq_w + l*DIMD*DIMD, wq_b + l*DIMD,
                                            wk_w + l*DIMD*DIMD, wk_b + l*DIMD,
                                            wv_w + l*DIMD*DIMD, wv_b + l*DIMD);
        k_attn<<<dim3(NN, HH, NB), 256>>>(mask, wd_b + l*HH);
        k_gemm64<<<dim3(2, 6), 256>>>(xs, 1, wl_w + l*DIMD*DIMD, wl_b + l*DIMD, xs ? 3 : 4, nullptr);
        cbuf ^= 1;
        xs ^= 1;
    }
    k_gemm64<<<dim3(2, 6), 256>>>(xs, 0, fc_w, fc_b, 5, out);
}